// round 14
// baseline (speedup 1.0000x reference)
#include <cuda_runtime.h>
#include <cuda_fp16.h>
#include <cstdint>
#include <cstring>

#define LL   2048
#define HH   3072
#define NHH  24
#define DD   128
#define MLPD 12288
#define W1N  21504
#define CATN 15360
#define QKVN 9216

__device__ __forceinline__ uint32_t h2_u32(__half2 h){
    uint32_t u; memcpy(&u, &h, 4); return u;
}
__device__ __forceinline__ __half2 u32_h2(uint32_t u){
    __half2 h; memcpy(&h, &u, 4); return h;
}
__device__ __forceinline__ uint32_t smem_u32(const void* p){
    uint32_t a; asm("{ .reg .u64 t; cvta.to.shared.u64 t, %1; cvt.u32.u64 %0, t; }" : "=r"(a) : "l"(p));
    return a;
}
__device__ __forceinline__ float ex2f(float x){
    float r; asm("ex2.approx.f32 %0, %1;" : "=f"(r) : "f"(x)); return r;
}
__device__ __forceinline__ uint32_t ex2_h2(uint32_t x){
    uint32_t r; asm("ex2.approx.f16x2 %0, %1;" : "=r"(r) : "r"(x)); return r;
}
__device__ __forceinline__ float tanh_ap(float x){
    float r; asm("tanh.approx.f32 %0, %1;" : "=f"(r) : "f"(x)); return r;
}
__device__ __forceinline__ float gelu_f(float v){
    float c = 0.7978845608028654f * (v + 0.044715f*v*v*v);
    return 0.5f*v*(1.f + tanh_ap(c));
}
__device__ __forceinline__ void mma_f16(float* c, const uint32_t* a, const uint32_t* b){
    asm volatile("mma.sync.aligned.m16n8k16.row.col.f32.f16.f16.f32 "
        "{%0,%1,%2,%3}, {%4,%5,%6,%7}, {%8,%9}, {%0,%1,%2,%3};"
        : "+f"(c[0]), "+f"(c[1]), "+f"(c[2]), "+f"(c[3])
        : "r"(a[0]), "r"(a[1]), "r"(a[2]), "r"(a[3]), "r"(b[0]), "r"(b[1]));
}
__device__ __forceinline__ void ldsm_x4(uint32_t* r, uint32_t a){
    asm volatile("ldmatrix.sync.aligned.m8n8.x4.shared.b16 {%0,%1,%2,%3}, [%4];"
        : "=r"(r[0]), "=r"(r[1]), "=r"(r[2]), "=r"(r[3]) : "r"(a));
}
__device__ __forceinline__ void ldsm_x4t(uint32_t* r, uint32_t a){
    asm volatile("ldmatrix.sync.aligned.m8n8.x4.trans.shared.b16 {%0,%1,%2,%3}, [%4];"
        : "=r"(r[0]), "=r"(r[1]), "=r"(r[2]), "=r"(r[3]) : "r"(a));
}

// ---------------- scratch ----------------
__device__ float  g_sv[HH];
__device__ float  g_mod[3*HH];
__device__ __half g_xmodh[(size_t)LL*HH];
__device__ __half g_qh[(size_t)NHH*LL*DD];
__device__ __half g_kh[(size_t)NHH*LL*DD];
__device__ __half g_vh[(size_t)NHH*LL*DD];
__device__ __half g_cath[(size_t)LL*CATN];
__device__ __half g_w1h[(size_t)HH*W1N];
__device__ __half g_w2h[(size_t)CATN*HH];

// ---------------- prep: conv w1 + conv w2 + silu + mod init ---------------
#define N4W1 ((int)((size_t)HH*W1N/4))
#define N4W2 ((int)((size_t)CATN*HH/4))
#define NB1  ((N4W1 + 255)/256)
#define NB2  ((N4W2 + 255)/256)
__global__ void prep(const float4* __restrict__ w1, uint2* __restrict__ o1,
                     const float4* __restrict__ w2, uint2* __restrict__ o2,
                     const float* __restrict__ vec, const float* __restrict__ b){
    const int bid = blockIdx.x;
    const int tid = threadIdx.x;
    if (bid < NB1 + NB2){
        const bool w1p = bid < NB1;
        int i = (w1p ? bid : bid - NB1)*256 + tid;
        int n = w1p ? N4W1 : N4W2;
        if (i < n){
            float4 v = w1p ? w1[i] : w2[i];
            __half2 a = __floats2half2_rn(v.x, v.y);
            __half2 c = __floats2half2_rn(v.z, v.w);
            uint2 o; memcpy(&o.x, &a, 4); memcpy(&o.y, &c, 4);
            if (w1p) o1[i] = o; else o2[i] = o;
        }
    } else {
        int i = (bid - NB1 - NB2)*256 + tid;
        if (i < HH){
            float t = vec[i];
            g_sv[i] = t / (1.f + expf(-t));
        }
        if (i < QKVN) g_mod[i] = b[i];
    }
}

// ---------------- K-split GEMV (float4 per thread) ----------------
__global__ __launch_bounds__(256) void mod_gemv(const float* __restrict__ W){
    const int j  = (blockIdx.x*256 + threadIdx.x)*4;
    const int k0 = blockIdx.y*256;
    __shared__ float svs[256];
    svs[threadIdx.x] = g_sv[k0 + threadIdx.x];
    __syncthreads();
    float a0 = 0.f, a1 = 0.f, a2 = 0.f, a3 = 0.f;
    #pragma unroll 4
    for (int i = 0; i < 256; i++){
        float4 w = *(const float4*)(W + (size_t)(k0+i)*QKVN + j);
        a0 = fmaf(svs[i], w.x, a0);
        a1 = fmaf(svs[i], w.y, a1);
        a2 = fmaf(svs[i], w.z, a2);
        a3 = fmaf(svs[i], w.w, a3);
    }
    atomicAdd(&g_mod[j],   a0);
    atomicAdd(&g_mod[j+1], a1);
    atomicAdd(&g_mod[j+2], a2);
    atomicAdd(&g_mod[j+3], a3);
}

// ---------------- LayerNorm + modulate (half output, 384 thr) -------------
__global__ __launch_bounds__(384) void ln_mod(const float* __restrict__ x,
                                              const float* __restrict__ lns,
                                              const float* __restrict__ lnb){
    const int l = blockIdx.x;
    const int tid = threadIdx.x;
    __shared__ float xs[HH];
    __shared__ float rsum[24];
    float s = 0.f, ss = 0.f;
    #pragma unroll
    for (int t = 0; t < 2; t++){
        int i = tid*4 + t*1536;
        float4 v = *(const float4*)(x + (size_t)l*HH + i);
        *(float4*)(xs + i) = v;
        s += v.x + v.y + v.z + v.w;
        ss = fmaf(v.x, v.x, ss); ss = fmaf(v.y, v.y, ss);
        ss = fmaf(v.z, v.z, ss); ss = fmaf(v.w, v.w, ss);
    }
    #pragma unroll
    for (int w = 1; w < 32; w <<= 1){
        s  += __shfl_xor_sync(0xffffffffu, s,  w);
        ss += __shfl_xor_sync(0xffffffffu, ss, w);
    }
    int wid = tid >> 5;
    if ((tid & 31) == 0){ rsum[wid] = s; rsum[wid + 12] = ss; }
    __syncthreads();
    s = 0.f; ss = 0.f;
    #pragma unroll
    for (int w = 0; w < 12; w++){ s += rsum[w]; ss += rsum[w + 12]; }
    const float mu   = s  * (1.f/(float)HH);
    const float var  = ss * (1.f/(float)HH) - mu*mu;
    const float rstd = rsqrtf(var + 1e-6f);
    #pragma unroll
    for (int t = 0; t < 2; t++){
        int i = tid*4 + t*1536;
        float4 v  = *(const float4*)(xs + i);
        float4 lv = *(const float4*)(lns + i);
        float4 bv = *(const float4*)(lnb + i);
        float4 sc = *(const float4*)(g_mod + HH + i);
        float4 sh = *(const float4*)(g_mod + i);
        float o0 = (1.f+sc.x)*((v.x-mu)*rstd*lv.x + bv.x) + sh.x;
        float o1 = (1.f+sc.y)*((v.y-mu)*rstd*lv.y + bv.y) + sh.y;
        float o2 = (1.f+sc.z)*((v.z-mu)*rstd*lv.z + bv.z) + sh.z;
        float o3 = (1.f+sc.w)*((v.w-mu)*rstd*lv.w + bv.w) + sh.w;
        uint2 o;
        __half2 ha = __floats2half2_rn(o0, o1);
        __half2 hb = __floats2half2_rn(o2, o3);
        memcpy(&o.x, &ha, 4); memcpy(&o.y, &hb, 4);
        *(uint2*)(g_xmodh + (size_t)l*HH + i) = o;
    }
}

// ---------------- shared GEMM geometry: 128x128 tile, 3-stage, occ 2 ------
#define MG_ARB   144
#define MG_BRB   272
#define G2_BOFF  (128*MG_ARB)                 // 18432
#define G2_STAGE (G2_BOFF + 64*MG_BRB)        // 35840
#define G2_SMEM  (3*G2_STAGE)                 // 107520

// ======== GEMM1 mainloop body (shared by qkv kernel and fused kernel) =====
// computes c[2][8][4] for (m0, n0); A=g_xmodh, B=g_w1h; adds bias.
__device__ __forceinline__ void g1_main(char* smc, int m0, int n0,
                                        const __half* __restrict__ A,
                                        const __half* __restrict__ B,
                                        const float* __restrict__ bias,
                                        float c[2][8][4])
{
    const uint32_t smb = smem_u32(smc);
    const int tid  = threadIdx.x;
    const int wid  = tid >> 5;
    const int lane = tid & 31;
    const int tig  = lane & 3;
    const int m0w = (wid & 3) * 32;
    const int n0w = (wid >> 2) * 64;
    const int K = HH, N = W1N, NIT = HH/64;

    const char* gp[8];
    uint32_t sof[8];
    size_t gstep[8];
    #pragma unroll
    for (int i = 0; i < 8; i++){
        int idx = i*256 + tid;
        if (idx < 1024){
            int row = idx >> 3, seg = idx & 7;
            gp[i]   = (const char*)(A + (size_t)(m0 + row)*K) + seg*16;
            sof[i]  = (uint32_t)(row*MG_ARB + seg*16);
            gstep[i] = 128;
        } else {
            int t = idx - 1024;
            int row = t >> 4, seg = t & 15;
            gp[i]   = (const char*)(B + (size_t)row*N + n0) + seg*16;
            sof[i]  = (uint32_t)(G2_BOFF + row*MG_BRB + seg*16);
            gstep[i] = (size_t)64*N*2;
        }
    }

#define GX_LOAD(IT, ST) do { \
        const uint32_t _sb = smb + (uint32_t)(ST)*G2_STAGE; \
        _Pragma("unroll") \
        for (int _i = 0; _i < 8; _i++){ \
            asm volatile("cp.async.cg.shared.global [%0], [%1], 16;" \
                :: "r"(_sb + sof[_i]), "l"(gp[_i] + (size_t)(IT)*gstep[_i]) : "memory"); \
        } \
        asm volatile("cp.async.commit_group;" ::: "memory"); \
    } while(0)

    #pragma unroll
    for (int mt = 0; mt < 2; mt++)
        #pragma unroll
        for (int nt = 0; nt < 8; nt++)
            #pragma unroll
            for (int q = 0; q < 4; q++) c[mt][nt][q] = 0.f;

    const uint32_t aoff  = (uint32_t)((lane & 15)*MG_ARB + ((lane >> 4) & 1)*16);
    const uint32_t boff4 = (uint32_t)(G2_BOFF + (lane & 15)*MG_BRB + ((lane >> 4) & 1)*16 + n0w*2);

    GX_LOAD(0, 0);
    GX_LOAD(1, 1);

    int s = 0, sl = 2;
    for (int it = 0; it < NIT; ++it){
        if (it == NIT-1) asm volatile("cp.async.wait_group 0;" ::: "memory");
        else             asm volatile("cp.async.wait_group 1;" ::: "memory");
        __syncthreads();
        if (it + 2 < NIT) GX_LOAD(it + 2, sl);

        const uint32_t sb = smb + (uint32_t)s*G2_STAGE;
        #pragma unroll
        for (int k16 = 0; k16 < 4; k16++){
            uint32_t a[2][4];
            #pragma unroll
            for (int mt = 0; mt < 2; mt++)
                ldsm_x4(a[mt], sb + (uint32_t)((m0w + mt*16)*MG_ARB) + aoff + k16*32);
            uint32_t b[8][2];
            #pragma unroll
            for (int u = 0; u < 4; u++)
                ldsm_x4t(&b[2*u][0], sb + boff4 + (uint32_t)(k16*16*MG_BRB) + u*32);
            #pragma unroll
            for (int mt = 0; mt < 2; mt++)
                #pragma unroll
                for (int nt = 0; nt < 8; nt++)
                    mma_f16(c[mt][nt], a[mt], b[nt]);
        }
        s  = (s  == 2) ? 0 : s  + 1;
        sl = (sl == 2) ? 0 : sl + 1;
    }

    #pragma unroll
    for (int nt = 0; nt < 8; nt++){
        const int n = n0 + n0w + nt*8 + 2*tig;
        const float b0 = __ldg(bias + n), b1 = __ldg(bias + n + 1);
        #pragma unroll
        for (int mt = 0; mt < 2; mt++){
            c[mt][nt][0] += b0; c[mt][nt][1] += b1;
            c[mt][nt][2] += b0; c[mt][nt][3] += b1;
        }
    }
}

// ---------------- GEMM1-qkv: rmsnorm + rope epilogue -----------------------
__global__ __launch_bounds__(256, 2)
void gemm1_qkv(const __half* __restrict__ A, const __half* __restrict__ B,
               const float* __restrict__ bias,
               const float* __restrict__ pe,
               const float* __restrict__ qsc, const float* __restrict__ ksc)
{
    extern __shared__ char smc[];
    const int m0 = blockIdx.x * 128;
    const int n0 = blockIdx.y * 128;
    const int tid  = threadIdx.x;
    const int wid  = tid >> 5;
    const int lane = tid & 31;
    const int g    = lane >> 2;
    const int tig  = lane & 3;
    const int m0w = (wid & 3) * 32;
    const int n0w = (wid >> 2) * 64;

    float c[2][8][4];
    g1_main(smc, m0, n0, A, B, bias, c);

    const int ht = n0 / HH;                 // 0=q, 1=k, 2=v
    const int nh = (n0 - ht*HH) >> 7;

    if (ht == 2){
        __half* dst = g_vh + (size_t)nh*LL*DD;
        #pragma unroll
        for (int mt = 0; mt < 2; mt++){
            const int m = m0 + m0w + mt*16 + g;
            #pragma unroll
            for (int nt = 0; nt < 8; nt++){
                const int nl = n0w + nt*8 + 2*tig;
                *(uint32_t*)(dst + (size_t)m*DD + nl)
                    = h2_u32(__floats2half2_rn(c[mt][nt][0], c[mt][nt][1]));
                *(uint32_t*)(dst + (size_t)(m+8)*DD + nl)
                    = h2_u32(__floats2half2_rn(c[mt][nt][2], c[mt][nt][3]));
            }
        }
        return;
    }

    // Q/K: RMSNorm over 128 cols + RoPE
    float* red = (float*)smc;
    float sA[2], sB[2];
    #pragma unroll
    for (int mt = 0; mt < 2; mt++){
        float a = 0.f, b = 0.f;
        #pragma unroll
        for (int nt = 0; nt < 8; nt++){
            a = fmaf(c[mt][nt][0], c[mt][nt][0], a);
            a = fmaf(c[mt][nt][1], c[mt][nt][1], a);
            b = fmaf(c[mt][nt][2], c[mt][nt][2], b);
            b = fmaf(c[mt][nt][3], c[mt][nt][3], b);
        }
        a += __shfl_xor_sync(0xffffffffu, a, 1);
        a += __shfl_xor_sync(0xffffffffu, a, 2);
        b += __shfl_xor_sync(0xffffffffu, b, 1);
        b += __shfl_xor_sync(0xffffffffu, b, 2);
        sA[mt] = a; sB[mt] = b;
    }
    __syncthreads();
    if (tig == 0){
        #pragma unroll
        for (int mt = 0; mt < 2; mt++){
            red[wid*32 + mt*16 + g]     = sA[mt];
            red[wid*32 + mt*16 + g + 8] = sB[mt];
        }
    }
    __syncthreads();
    const int pw = wid ^ 4;
    float rrA[2], rrB[2];
    #pragma unroll
    for (int mt = 0; mt < 2; mt++){
        float ta = red[wid*32 + mt*16 + g]     + red[pw*32 + mt*16 + g];
        float tb = red[wid*32 + mt*16 + g + 8] + red[pw*32 + mt*16 + g + 8];
        rrA[mt] = rsqrtf(ta*(1.f/128.f) + 1e-6f);
        rrB[mt] = rsqrtf(tb*(1.f/128.f) + 1e-6f);
    }

    const float* sc = (ht == 0) ? qsc : ksc;
    const float post = (ht == 0) ? (0.08838834764831845f * 1.4426950408889634f) : 1.f;
    __half* dst = ((ht == 0) ? g_qh : g_kh) + (size_t)nh*LL*DD;

    #pragma unroll
    for (int mt = 0; mt < 2; mt++){
        const int mA = m0 + m0w + mt*16 + g;
        const int mB = mA + 8;
        #pragma unroll
        for (int nt = 0; nt < 8; nt++){
            const int nl = n0w + nt*8 + 2*tig;
            const int d2 = nl >> 1;
            const float s0 = __ldg(sc + nl), s1 = __ldg(sc + nl + 1);
            {
                const float4 r = *(const float4*)(pe + ((size_t)mA*64 + d2)*4);
                float e = c[mt][nt][0]*rrA[mt]*s0;
                float o = c[mt][nt][1]*rrA[mt]*s1;
                *(uint32_t*)(dst + (size_t)mA*DD + nl)
                    = h2_u32(__floats2half2_rn((r.x*e + r.y*o)*post, (r.z*e + r.w*o)*post));
            }
            {
                const float4 r = *(const float4*)(pe + ((size_t)mB*64 + d2)*4);
                float e = c[mt][nt][2]*rrB[mt]*s0;
                float o = c[mt][nt][3]*rrB[mt]*s1;
                *(uint32_t*)(dst + (size_t)mB*DD + nl)
                    = h2_u32(__floats2half2_rn((r.x*e + r.y*o)*post, (r.z*e + r.w*o)*post));
            }
        }
    }
}

// ---------------- attention body (device) ----------------------------------
#define AQ_RB 272
#define AKV0  (128*AQ_RB)
#define AKV_STAGE (64*AQ_RB*2)
#define AV_IN 17408
#define NKT (LL/64)

__device__ __forceinline__ void attn_body(char* smc, int abid){
    const uint32_t smb = smem_u32(smc);
    const int tid  = threadIdx.x;
    const int wid  = tid >> 5;
    const int lane = tid & 31;
    const int nh = abid >> 4;
    const int q0 = (abid & 15) * 128;
    const __half* Qh = g_qh + (size_t)nh*LL*DD;
    const __half* Kh = g_kh + (size_t)nh*LL*DD;
    const __half* Vh = g_vh + (size_t)nh*LL*DD;

#define ATT_LOAD(IT, ST) do { \
        const uint32_t _sb = smb + AKV0 + (uint32_t)(ST)*AKV_STAGE; \
        const __half* _kb = Kh + (size_t)(IT)*64*DD; \
        const __half* _vb = Vh + (size_t)(IT)*64*DD; \
        _Pragma("unroll") \
        for (int _i = 0; _i < 8; _i++){ \
            int _idx = _i*256 + tid; \
            int _t = _idx & 1023; \
            int _r = _t >> 4, _sg = _t & 15; \
            const char* _g = (const char*)((_idx < 1024 ? _kb : _vb) + (size_t)_r*DD) + _sg*16; \
            uint32_t _sa = _sb + (_idx < 1024 ? 0u : (uint32_t)AV_IN) + (uint32_t)(_r*AQ_RB + _sg*16); \
            asm volatile("cp.async.cg.shared.global [%0], [%1], 16;" :: "r"(_sa), "l"(_g) : "memory"); \
        } \
        asm volatile("cp.async.commit_group;" ::: "memory"); \
    } while(0)

    ATT_LOAD(0, 0);
    ATT_LOAD(1, 1);

    #pragma unroll
    for (int i = 0; i < 8; i++){
        int idx = i*256 + tid;
        int r = idx >> 4, s = idx & 15;
        uint4 v = *(const uint4*)((const char*)(Qh + (size_t)(q0+r)*DD) + s*16);
        *(uint4*)(smc + r*AQ_RB + s*16) = v;
    }

    float o[16][4];
    #pragma unroll
    for (int nt = 0; nt < 16; nt++)
        #pragma unroll
        for (int q = 0; q < 4; q++) o[nt][q] = 0.f;
    float m0 = -1e30f, m1 = -1e30f, l0 = 0.f, l1 = 0.f;

    const uint32_t aoffQ = smb + (uint32_t)((wid*16 + (lane & 15))*AQ_RB + ((lane >> 4) & 1)*16);
    const uint32_t kbase4 = (uint32_t)((((lane >> 4) & 1)*8 + (lane & 7))*AQ_RB + ((lane >> 3) & 1)*16);
    const uint32_t vbase4 = (uint32_t)((lane & 15)*AQ_RB + ((lane >> 4) & 1)*16);

    int st = 0;
    for (int kt = 0; kt < NKT; kt++){
        if (kt == NKT-1) asm volatile("cp.async.wait_group 0;" ::: "memory");
        else             asm volatile("cp.async.wait_group 1;" ::: "memory");
        __syncthreads();

        const uint32_t kvb = smb + AKV0 + (uint32_t)st*AKV_STAGE;

        float s[8][4];
        #pragma unroll
        for (int nt = 0; nt < 8; nt++)
            #pragma unroll
            for (int q = 0; q < 4; q++) s[nt][q] = 0.f;
        #pragma unroll
        for (int k16 = 0; k16 < 8; k16++){
            uint32_t a[4];
            ldsm_x4(a, aoffQ + k16*32);
            #pragma unroll
            for (int u = 0; u < 4; u++){
                uint32_t bb[4];
                ldsm_x4(bb, kvb + kbase4 + (uint32_t)(u*16*AQ_RB) + k16*32);
                mma_f16(s[2*u],   a, bb);
                mma_f16(s[2*u+1], a, bb+2);
            }
        }

        float mx0 = -1e30f, mx1 = -1e30f;
        #pragma unroll
        for (int nt = 0; nt < 8; nt++){
            mx0 = fmaxf(mx0, fmaxf(s[nt][0], s[nt][1]));
            mx1 = fmaxf(mx1, fmaxf(s[nt][2], s[nt][3]));
        }
        mx0 = fmaxf(mx0, __shfl_xor_sync(0xffffffffu, mx0, 1));
        mx0 = fmaxf(mx0, __shfl_xor_sync(0xffffffffu, mx0, 2));
        mx1 = fmaxf(mx1, __shfl_xor_sync(0xffffffffu, mx1, 1));
        mx1 = fmaxf(mx1, __shfl_xor_sync(0xffffffffu, mx1, 2));
        const float mn0 = fmaxf(m0, mx0), mn1 = fmaxf(m1, mx1);
        const float al0 = ex2f(m0 - mn0), al1 = ex2f(m1 - mn1);
        m0 = mn0; m1 = mn1;
        float rs0 = 0.f, rs1 = 0.f;
        uint32_t ph[8][2];
        #pragma unroll
        for (int nt = 0; nt < 8; nt++){
            ph[nt][0] = ex2_h2(h2_u32(__floats2half2_rn(s[nt][0]-mn0, s[nt][1]-mn0)));
            ph[nt][1] = ex2_h2(h2_u32(__floats2half2_rn(s[nt][2]-mn1, s[nt][3]-mn1)));
            float2 f0 = __half22float2(u32_h2(ph[nt][0]));
            float2 f1 = __half22float2(u32_h2(ph[nt][1]));
            rs0 += f0.x + f0.y;
            rs1 += f1.x + f1.y;
        }
        rs0 += __shfl_xor_sync(0xffffffffu, rs0, 1);
        rs0 += __shfl_xor_sync(0xffffffffu, rs0, 2);
        rs1 += __shfl_xor_sync(0xffffffffu, rs1, 1);
        rs1 += __shfl_xor_sync(0xffffffffu, rs1, 2);
        l0 = l0*al0 + rs0;
        l1 = l1*al1 + rs1;
        #pragma unroll
        for (int nt = 0; nt < 16; nt++){
            o[nt][0] *= al0; o[nt][1] *= al0;
            o[nt][2] *= al1; o[nt][3] *= al1;
        }

        #pragma unroll
        for (int c16 = 0; c16 < 4; c16++){
            uint32_t pa[4] = { ph[2*c16][0], ph[2*c16][1],
                               ph[2*c16+1][0], ph[2*c16+1][1] };
            #pragma unroll
            for (int u = 0; u < 8; u++){
                uint32_t bb[4];
                ldsm_x4t(bb, kvb + AV_IN + vbase4 + (uint32_t)(c16*16*AQ_RB) + u*32);
                mma_f16(o[2*u],   pa, bb);
                mma_f16(o[2*u+1], pa, bb+2);
            }
        }

        __syncthreads();
        if (kt + 2 < NKT) ATT_LOAD(kt + 2, st);
        st ^= 1;
    }

    const float rl0 = 1.0f / l0, rl1 = 1.0f / l1;
    const int g = lane >> 2, tig = lane & 3;
    const int r0 = q0 + wid*16 + g, r1 = r0 + 8;
    #pragma unroll
    for (int nt = 0; nt < 16; nt++){
        const int col = nh*DD + nt*8 + 2*tig;
        *(uint32_t*)(g_cath + (size_t)r0*CATN + col)
            = h2_u32(__floats2half2_rn(o[nt][0]*rl0, o[nt][1]*rl0));
        *(uint32_t*)(g_cath + (size_t)r1*CATN + col)
            = h2_u32(__floats2half2_rn(o[nt][2]*rl1, o[nt][3]*rl1));
    }
}

// ---------------- fused middle: attention (bid<384) + gemm1-mlp -----------
__global__ __launch_bounds__(256, 2)
void fused_mid(const __half* __restrict__ A, const __half* __restrict__ B,
               const float* __restrict__ bias)
{
    extern __shared__ char smc[];
    const int bid = blockIdx.x;
    if (bid < 384){
        attn_body(smc, bid);
        return;
    }
    const int idx = bid - 384;               // 0..1535
    const int m0 = (idx & 15) * 128;
    const int n0 = QKVN + (idx >> 4) * 128;

    float c[2][8][4];
    g1_main(smc, m0, n0, A, B, bias, c);

    const int tid  = threadIdx.x;
    const int wid  = tid >> 5;
    const int lane = tid & 31;
    const int g    = lane >> 2;
    const int tig  = lane & 3;
    const int m0w = (wid & 3) * 32;
    const int n0w = (wid >> 2) * 64;
    const int nc0 = HH + (n0 - QKVN);
    #pragma unroll
    for (int mt = 0; mt < 2; mt++){
        const int m = m0 + m0w + mt*16 + g;
        #pragma unroll
        for (int nt = 0; nt < 8; nt++){
            const int nl = n0w + nt*8 + 2*tig;
            float v0 = gelu_f(c[mt][nt][0]);
            float v1 = gelu_f(c[mt][nt][1]);
            float v2 = gelu_f(c[mt][nt][2]);
            float v3 = gelu_f(c[mt][nt][3]);
            *(uint32_t*)(g_cath + (size_t)m*CATN + nc0 + nl)
                = h2_u32(__floats2half2_rn(v0, v1));
            *(uint32_t*)(g_cath + (size_t)(m+8)*CATN + nc0 + nl)
                = h2_u32(__floats2half2_rn(v2, v3));
        }
    }
}

// ---------------- GEMM2: gated residual epilogue ---------------------------
__global__ __launch_bounds__(256, 2)
void gemm2_f16(const __half* __restrict__ A, const __half* __restrict__ B,
               const float* __restrict__ bias, float* __restrict__ Cf,
               int N, int K, int NIT,
               const float* __restrict__ xres, const float* __restrict__ gate)
{
    extern __shared__ char smc[];
    const uint32_t smb = smem_u32(smc);
    const int tid  = threadIdx.x;
    const int wid  = tid >> 5;
    const int lane = tid & 31;
    const int g    = lane >> 2;
    const int tig  = lane & 3;
    const int m0 = blockIdx.x * 128;
    const int n0 = blockIdx.y * 128;
    const int m0w = (wid & 3) * 32;
    const int n0w = (wid >> 2) * 64;

    const char* gp[8];
    uint32_t sof[8];
    size_t gstep[8];
    #pragma unroll
    for (int i = 0; i < 8; i++){
        int idx = i*256 + tid;
        if (idx < 1024){
            int row = idx >> 3, seg = idx & 7;
            gp[i]   = (const char*)(A + (size_t)(m0 + row)*K) + seg*16;
            sof[i]  = (uint32_t)(row*MG_ARB + seg*16);
            gstep[i] = 128;
        } else {
            int t = idx - 1024;
            int row = t >> 4, seg = t & 15;
            gp[i]   = (const char*)(B + (size_t)row*N + n0) + seg*16;
            sof[i]  = (uint32_t)(G2_BOFF + row*MG_BRB + seg*16);
            gstep[i] = (size_t)64*N*2;
        }
    }

#define G2_LOAD(IT, ST) do { \
        const uint32_t _sb = smb + (uint32_t)(ST)*G2_STAGE; \
        _Pragma("unroll") \
        for (int _i = 0; _i < 8; _i++){ \
            asm volatile("cp.async.cg.shared.global [%0], [%1], 16;" \
                :: "r"(_sb + sof[_i]), "l"(gp[_i] + (size_t)(IT)*gstep[_i]) : "memory"); \
        } \
        asm volatile("cp.async.commit_group;" ::: "memory"); \
    } while(0)

    float c[2][8][4];
    #pragma unroll
    for (int mt = 0; mt < 2; mt++)
        #pragma unroll
        for (int nt = 0; nt < 8; nt++)
            #pragma unroll
            for (int q = 0; q < 4; q++) c[mt][nt][q] = 0.f;

    const uint32_t aoff  = (uint32_t)((lane & 15)*MG_ARB + ((lane >> 4) & 1)*16);
    const uint32_t boff4 = (uint32_t)(G2_BOFF + (lane & 15)*MG_BRB + ((lane >> 4) & 1)*16 + n0w*2);

    G2_LOAD(0, 0);
    G2_LOAD(1, 1);

    int s = 0, sl = 2;
    for (int it = 0; it < NIT; ++it){
        if (it == NIT-1) asm volatile("cp.async.wait_group 0;" ::: "memory");
        else             asm volatile("cp.async.wait_group 1;" ::: "memory");
        __syncthreads();
        if (it + 2 < NIT) G2_LOAD(it + 2, sl);

        const uint32_t sb = smb + (uint32_t)s*G2_STAGE;
        #pragma unroll
        for (int k16 = 0; k16 < 4; k16++){
            uint32_t a[2][4];
            #pragma unroll
            for (int mt = 0; mt < 2; mt++)
                ldsm_x4(a[mt], sb + (uint32_t)((m0w + mt*16)*MG_ARB) + aoff + k16*32);
            uint32_t b[8][2];
            #pragma unroll
            for (int u = 0; u < 4; u++)
                ldsm_x4t(&b[2*u][0], sb + boff4 + (uint32_t)(k16*16*MG_BRB) + u*32);
            #pragma unroll
            for (int mt = 0; mt < 2; mt++)
                #pragma unroll
                for (int nt = 0; nt < 8; nt++)
                    mma_f16(c[mt][nt], a[mt], b[nt]);
        }
        s  = (s  == 2) ? 0 : s  + 1;
        sl = (sl == 2) ? 0 : sl + 1;
    }

    #pragma unroll
    for (int mt = 0; mt < 2; mt++){
        const int m = m0 + m0w + mt*16 + g;
        #pragma unroll
        for (int nt = 0; nt < 8; nt++){
            const int n = n0 + n0w + nt*8 + 2*tig;
            const float b0 = __ldg(bias + n), b1 = __ldg(bias + n + 1);
            const float g0 = __ldg(gate + n), g1 = __ldg(gate + n + 1);
            float v0 = xres[(size_t)m*N + n]       + g0*(c[mt][nt][0] + b0);
            float v1 = xres[(size_t)m*N + n + 1]   + g1*(c[mt][nt][1] + b1);
            float v2 = xres[(size_t)(m+8)*N + n]   + g0*(c[mt][nt][2] + b0);
            float v3 = xres[(size_t)(m+8)*N + n+1] + g1*(c[mt][nt][3] + b1);
            *(float2*)(Cf + (size_t)m*N + n)     = make_float2(v0, v1);
            *(float2*)(Cf + (size_t)(m+8)*N + n) = make_float2(v2, v3);
        }
    }
}

// ---------------- launch --------------------------------------------------
extern "C" void kernel_launch(void* const* d_in, const int* in_sizes, int n_in,
                              void* d_out, int out_size){
    (void)in_sizes; (void)n_in; (void)out_size;
    const float* x       = (const float*)d_in[0];
    const float* vec     = (const float*)d_in[1];
    const float* pe      = (const float*)d_in[2];
    const float* mod_w   = (const float*)d_in[3];
    const float* mod_b   = (const float*)d_in[4];
    const float* ln_s    = (const float*)d_in[5];
    const float* ln_b    = (const float*)d_in[6];
    const float* w1      = (const float*)d_in[7];
    const float* b1      = (const float*)d_in[8];
    const float* q_scale = (const float*)d_in[9];
    const float* k_scale = (const float*)d_in[10];
    const float* w2      = (const float*)d_in[11];
    const float* b2      = (const float*)d_in[12];
    float* out = (float*)d_out;

    float *p_mod;
    __half *p_xmodh, *p_cath, *p_w1h, *p_w2h;
    cudaGetSymbolAddress((void**)&p_xmodh, g_xmodh);
    cudaGetSymbolAddress((void**)&p_cath,  g_cath);
    cudaGetSymbolAddress((void**)&p_mod,   g_mod);
    cudaGetSymbolAddress((void**)&p_w1h,   g_w1h);
    cudaGetSymbolAddress((void**)&p_w2h,   g_w2h);

    cudaFuncSetAttribute(gemm1_qkv, cudaFuncAttributeMaxDynamicSharedMemorySize, G2_SMEM);
    cudaFuncSetAttribute(fused_mid, cudaFuncAttributeMaxDynamicSharedMemorySize, G2_SMEM);
    cudaFuncSetAttribute(gemm2_f16, cudaFuncAttributeMaxDynamicSharedMemorySize, G2_SMEM);

    prep<<<NB1 + NB2 + (QKVN + 255)/256, 256>>>((const float4*)w1, (uint2*)p_w1h,
                                                (const float4*)w2, (uint2*)p_w2h,
                                                vec, mod_b);
    mod_gemv<<<dim3(QKVN/1024, HH/256), 256>>>(mod_w);
    ln_mod  <<<LL, 384>>>(x, ln_s, ln_b);
    gemm1_qkv<<<dim3(LL/128, QKVN/128), 256, G2_SMEM>>>(p_xmodh, p_w1h, b1,
                                                        pe, q_scale, k_scale);
    fused_mid<<<384 + (LL/128)*(MLPD/128), 256, G2_SMEM>>>(p_xmodh, p_w1h, b1);
    gemm2_f16<<<dim3(LL/128, HH/128), 256, G2_SMEM>>>(p_cath, p_w2h, b2, out,
                                                      HH, CATN, CATN/64,
                                                      x, p_mod + 2*HH);
}

// round 15
// speedup vs baseline: 1.0232x; 1.0232x over previous
#include <cuda_runtime.h>
#include <cuda_fp16.h>
#include <cstdint>
#include <cstring>

#define LL   2048
#define HH   3072
#define NHH  24
#define DD   128
#define MLPD 12288
#define W1N  21504
#define CATN 15360
#define QKVN 9216

__device__ __forceinline__ uint32_t h2_u32(__half2 h){
    uint32_t u; memcpy(&u, &h, 4); return u;
}
__device__ __forceinline__ __half2 u32_h2(uint32_t u){
    __half2 h; memcpy(&h, &u, 4); return h;
}
__device__ __forceinline__ uint32_t smem_u32(const void* p){
    uint32_t a; asm("{ .reg .u64 t; cvta.to.shared.u64 t, %1; cvt.u32.u64 %0, t; }" : "=r"(a) : "l"(p));
    return a;
}
__device__ __forceinline__ float ex2f(float x){
    float r; asm("ex2.approx.f32 %0, %1;" : "=f"(r) : "f"(x)); return r;
}
__device__ __forceinline__ uint32_t ex2_h2(uint32_t x){
    uint32_t r; asm("ex2.approx.f16x2 %0, %1;" : "=r"(r) : "r"(x)); return r;
}
__device__ __forceinline__ float tanh_ap(float x){
    float r; asm("tanh.approx.f32 %0, %1;" : "=f"(r) : "f"(x)); return r;
}
__device__ __forceinline__ float gelu_f(float v){
    float c = 0.7978845608028654f * (v + 0.044715f*v*v*v);
    return 0.5f*v*(1.f + tanh_ap(c));
}
__device__ __forceinline__ void mma_f16(float* c, const uint32_t* a, const uint32_t* b){
    asm volatile("mma.sync.aligned.m16n8k16.row.col.f32.f16.f16.f32 "
        "{%0,%1,%2,%3}, {%4,%5,%6,%7}, {%8,%9}, {%0,%1,%2,%3};"
        : "+f"(c[0]), "+f"(c[1]), "+f"(c[2]), "+f"(c[3])
        : "r"(a[0]), "r"(a[1]), "r"(a[2]), "r"(a[3]), "r"(b[0]), "r"(b[1]));
}
__device__ __forceinline__ void ldsm_x4(uint32_t* r, uint32_t a){
    asm volatile("ldmatrix.sync.aligned.m8n8.x4.shared.b16 {%0,%1,%2,%3}, [%4];"
        : "=r"(r[0]), "=r"(r[1]), "=r"(r[2]), "=r"(r[3]) : "r"(a));
}
__device__ __forceinline__ void ldsm_x4t(uint32_t* r, uint32_t a){
    asm volatile("ldmatrix.sync.aligned.m8n8.x4.trans.shared.b16 {%0,%1,%2,%3}, [%4];"
        : "=r"(r[0]), "=r"(r[1]), "=r"(r[2]), "=r"(r[3]) : "r"(a));
}

// ---------------- scratch ----------------
__device__ float  g_sv[HH];
__device__ float  g_mod[3*HH];
__device__ __half g_xmodh[(size_t)LL*HH];
__device__ __half g_qh[(size_t)NHH*LL*DD];
__device__ __half g_kh[(size_t)NHH*LL*DD];
__device__ __half g_vh[(size_t)NHH*LL*DD];
__device__ __half g_cath[(size_t)LL*CATN];
__device__ __half g_w1h[(size_t)HH*W1N];
__device__ __half g_w2h[(size_t)CATN*HH];

// ---------------- prep: conv w1 + conv w2 + silu/mod + zero d_out ---------
#define N4W1 ((int)((size_t)HH*W1N/4))
#define N4W2 ((int)((size_t)CATN*HH/4))
#define NB1  ((N4W1 + 255)/256)
#define NB2  ((N4W2 + 255)/256)
#define NBS  ((QKVN + 255)/256)
#define NZ4  ((int)((size_t)LL*HH/4))
#define NBZ  ((NZ4 + 255)/256)
__global__ void prep(const float4* __restrict__ w1, uint2* __restrict__ o1,
                     const float4* __restrict__ w2, uint2* __restrict__ o2,
                     const float* __restrict__ vec, const float* __restrict__ b,
                     float4* __restrict__ outz){
    const int bid = blockIdx.x;
    const int tid = threadIdx.x;
    if (bid < NB1 + NB2){
        const bool w1p = bid < NB1;
        int i = (w1p ? bid : bid - NB1)*256 + tid;
        int n = w1p ? N4W1 : N4W2;
        if (i < n){
            float4 v = w1p ? w1[i] : w2[i];
            __half2 a = __floats2half2_rn(v.x, v.y);
            __half2 c = __floats2half2_rn(v.z, v.w);
            uint2 o; memcpy(&o.x, &a, 4); memcpy(&o.y, &c, 4);
            if (w1p) o1[i] = o; else o2[i] = o;
        }
    } else if (bid < NB1 + NB2 + NBS){
        int i = (bid - NB1 - NB2)*256 + tid;
        if (i < HH){
            float t = vec[i];
            g_sv[i] = t / (1.f + expf(-t));
        }
        if (i < QKVN) g_mod[i] = b[i];
    } else {
        int i = (bid - NB1 - NB2 - NBS)*256 + tid;
        if (i < NZ4) outz[i] = make_float4(0.f, 0.f, 0.f, 0.f);
    }
}

// ---------------- K-split GEMV (float4 per thread) ----------------
__global__ __launch_bounds__(256) void mod_gemv(const float* __restrict__ W){
    const int j  = (blockIdx.x*256 + threadIdx.x)*4;
    const int k0 = blockIdx.y*256;
    __shared__ float svs[256];
    svs[threadIdx.x] = g_sv[k0 + threadIdx.x];
    __syncthreads();
    float a0 = 0.f, a1 = 0.f, a2 = 0.f, a3 = 0.f;
    #pragma unroll 4
    for (int i = 0; i < 256; i++){
        float4 w = *(const float4*)(W + (size_t)(k0+i)*QKVN + j);
        a0 = fmaf(svs[i], w.x, a0);
        a1 = fmaf(svs[i], w.y, a1);
        a2 = fmaf(svs[i], w.z, a2);
        a3 = fmaf(svs[i], w.w, a3);
    }
    atomicAdd(&g_mod[j],   a0);
    atomicAdd(&g_mod[j+1], a1);
    atomicAdd(&g_mod[j+2], a2);
    atomicAdd(&g_mod[j+3], a3);
}

// ---------------- LayerNorm + modulate (half output, 384 thr) -------------
__global__ __launch_bounds__(384) void ln_mod(const float* __restrict__ x,
                                              const float* __restrict__ lns,
                                              const float* __restrict__ lnb){
    const int l = blockIdx.x;
    const int tid = threadIdx.x;
    __shared__ float xs[HH];
    __shared__ float rsum[24];
    float s = 0.f, ss = 0.f;
    #pragma unroll
    for (int t = 0; t < 2; t++){
        int i = tid*4 + t*1536;
        float4 v = *(const float4*)(x + (size_t)l*HH + i);
        *(float4*)(xs + i) = v;
        s += v.x + v.y + v.z + v.w;
        ss = fmaf(v.x, v.x, ss); ss = fmaf(v.y, v.y, ss);
        ss = fmaf(v.z, v.z, ss); ss = fmaf(v.w, v.w, ss);
    }
    #pragma unroll
    for (int w = 1; w < 32; w <<= 1){
        s  += __shfl_xor_sync(0xffffffffu, s,  w);
        ss += __shfl_xor_sync(0xffffffffu, ss, w);
    }
    int wid = tid >> 5;
    if ((tid & 31) == 0){ rsum[wid] = s; rsum[wid + 12] = ss; }
    __syncthreads();
    s = 0.f; ss = 0.f;
    #pragma unroll
    for (int w = 0; w < 12; w++){ s += rsum[w]; ss += rsum[w + 12]; }
    const float mu   = s  * (1.f/(float)HH);
    const float var  = ss * (1.f/(float)HH) - mu*mu;
    const float rstd = rsqrtf(var + 1e-6f);
    #pragma unroll
    for (int t = 0; t < 2; t++){
        int i = tid*4 + t*1536;
        float4 v  = *(const float4*)(xs + i);
        float4 lv = *(const float4*)(lns + i);
        float4 bv = *(const float4*)(lnb + i);
        float4 sc = *(const float4*)(g_mod + HH + i);
        float4 sh = *(const float4*)(g_mod + i);
        float o0 = (1.f+sc.x)*((v.x-mu)*rstd*lv.x + bv.x) + sh.x;
        float o1 = (1.f+sc.y)*((v.y-mu)*rstd*lv.y + bv.y) + sh.y;
        float o2 = (1.f+sc.z)*((v.z-mu)*rstd*lv.z + bv.z) + sh.z;
        float o3 = (1.f+sc.w)*((v.w-mu)*rstd*lv.w + bv.w) + sh.w;
        uint2 o;
        __half2 ha = __floats2half2_rn(o0, o1);
        __half2 hb = __floats2half2_rn(o2, o3);
        memcpy(&o.x, &ha, 4); memcpy(&o.y, &hb, 4);
        *(uint2*)(g_xmodh + (size_t)l*HH + i) = o;
    }
}

// ---------------- shared GEMM geometry: 128x128 tile, 3-stage, occ 2 ------
#define MG_ARB   144
#define MG_BRB   272
#define G2_BOFF  (128*MG_ARB)                 // 18432
#define G2_STAGE (G2_BOFF + 64*MG_BRB)        // 35840
#define G2_SMEM  (3*G2_STAGE)                 // 107520

// ---------------- GEMM1: fused epilogue (qkv rmsnorm+rope | gelu) ---------
__global__ __launch_bounds__(256, 2)
void gemm1_f16(const __half* __restrict__ A, const __half* __restrict__ B,
               const float* __restrict__ bias,
               const float* __restrict__ pe,
               const float* __restrict__ qsc, const float* __restrict__ ksc,
               int N, int K, int NIT)
{
    extern __shared__ char smc[];
    const uint32_t smb = smem_u32(smc);
    const int tid  = threadIdx.x;
    const int wid  = tid >> 5;
    const int lane = tid & 31;
    const int g    = lane >> 2;
    const int tig  = lane & 3;
    const int m0 = blockIdx.x * 128;
    const int n0 = blockIdx.y * 128;
    const int m0w = (wid & 3) * 32;
    const int n0w = (wid >> 2) * 64;

    const char* gp[8];
    uint32_t sof[8];
    size_t gstep[8];
    #pragma unroll
    for (int i = 0; i < 8; i++){
        int idx = i*256 + tid;
        if (idx < 1024){
            int row = idx >> 3, seg = idx & 7;
            gp[i]   = (const char*)(A + (size_t)(m0 + row)*K) + seg*16;
            sof[i]  = (uint32_t)(row*MG_ARB + seg*16);
            gstep[i] = 128;
        } else {
            int t = idx - 1024;
            int row = t >> 4, seg = t & 15;
            gp[i]   = (const char*)(B + (size_t)row*N + n0) + seg*16;
            sof[i]  = (uint32_t)(G2_BOFF + row*MG_BRB + seg*16);
            gstep[i] = (size_t)64*N*2;
        }
    }

#define G1_LOAD(IT, ST) do { \
        const uint32_t _sb = smb + (uint32_t)(ST)*G2_STAGE; \
        _Pragma("unroll") \
        for (int _i = 0; _i < 8; _i++){ \
            asm volatile("cp.async.cg.shared.global [%0], [%1], 16;" \
                :: "r"(_sb + sof[_i]), "l"(gp[_i] + (size_t)(IT)*gstep[_i]) : "memory"); \
        } \
        asm volatile("cp.async.commit_group;" ::: "memory"); \
    } while(0)

    float c[2][8][4];
    #pragma unroll
    for (int mt = 0; mt < 2; mt++)
        #pragma unroll
        for (int nt = 0; nt < 8; nt++)
            #pragma unroll
            for (int q = 0; q < 4; q++) c[mt][nt][q] = 0.f;

    const uint32_t aoff  = (uint32_t)((lane & 15)*MG_ARB + ((lane >> 4) & 1)*16);
    const uint32_t boff4 = (uint32_t)(G2_BOFF + (lane & 15)*MG_BRB + ((lane >> 4) & 1)*16 + n0w*2);

    G1_LOAD(0, 0);
    G1_LOAD(1, 1);

    int s = 0, sl = 2;
    for (int it = 0; it < NIT; ++it){
        if (it == NIT-1) asm volatile("cp.async.wait_group 0;" ::: "memory");
        else             asm volatile("cp.async.wait_group 1;" ::: "memory");
        __syncthreads();
        if (it + 2 < NIT) G1_LOAD(it + 2, sl);

        const uint32_t sb = smb + (uint32_t)s*G2_STAGE;
        #pragma unroll
        for (int k16 = 0; k16 < 4; k16++){
            uint32_t a[2][4];
            #pragma unroll
            for (int mt = 0; mt < 2; mt++)
                ldsm_x4(a[mt], sb + (uint32_t)((m0w + mt*16)*MG_ARB) + aoff + k16*32);
            uint32_t b[8][2];
            #pragma unroll
            for (int u = 0; u < 4; u++)
                ldsm_x4t(&b[2*u][0], sb + boff4 + (uint32_t)(k16*16*MG_BRB) + u*32);
            #pragma unroll
            for (int mt = 0; mt < 2; mt++)
                #pragma unroll
                for (int nt = 0; nt < 8; nt++)
                    mma_f16(c[mt][nt], a[mt], b[nt]);
        }
        s  = (s  == 2) ? 0 : s  + 1;
        sl = (sl == 2) ? 0 : sl + 1;
    }

    #pragma unroll
    for (int nt = 0; nt < 8; nt++){
        const int n = n0 + n0w + nt*8 + 2*tig;
        const float b0 = __ldg(bias + n), b1 = __ldg(bias + n + 1);
        #pragma unroll
        for (int mt = 0; mt < 2; mt++){
            c[mt][nt][0] += b0; c[mt][nt][1] += b1;
            c[mt][nt][2] += b0; c[mt][nt][3] += b1;
        }
    }

    if (n0 >= QKVN){
        const int nc0 = HH + (n0 - QKVN);
        #pragma unroll
        for (int mt = 0; mt < 2; mt++){
            const int m = m0 + m0w + mt*16 + g;
            #pragma unroll
            for (int nt = 0; nt < 8; nt++){
                const int nl = n0w + nt*8 + 2*tig;
                float v0 = gelu_f(c[mt][nt][0]);
                float v1 = gelu_f(c[mt][nt][1]);
                float v2 = gelu_f(c[mt][nt][2]);
                float v3 = gelu_f(c[mt][nt][3]);
                *(uint32_t*)(g_cath + (size_t)m*CATN + nc0 + nl)
                    = h2_u32(__floats2half2_rn(v0, v1));
                *(uint32_t*)(g_cath + (size_t)(m+8)*CATN + nc0 + nl)
                    = h2_u32(__floats2half2_rn(v2, v3));
            }
        }
        return;
    }

    const int ht = n0 / HH;
    const int nh = (n0 - ht*HH) >> 7;

    if (ht == 2){
        __half* dst = g_vh + (size_t)nh*LL*DD;
        #pragma unroll
        for (int mt = 0; mt < 2; mt++){
            const int m = m0 + m0w + mt*16 + g;
            #pragma unroll
            for (int nt = 0; nt < 8; nt++){
                const int nl = n0w + nt*8 + 2*tig;
                *(uint32_t*)(dst + (size_t)m*DD + nl)
                    = h2_u32(__floats2half2_rn(c[mt][nt][0], c[mt][nt][1]));
                *(uint32_t*)(dst + (size_t)(m+8)*DD + nl)
                    = h2_u32(__floats2half2_rn(c[mt][nt][2], c[mt][nt][3]));
            }
        }
        return;
    }

    float* red = (float*)smc;
    float sA[2], sB[2];
    #pragma unroll
    for (int mt = 0; mt < 2; mt++){
        float a = 0.f, b = 0.f;
        #pragma unroll
        for (int nt = 0; nt < 8; nt++){
            a = fmaf(c[mt][nt][0], c[mt][nt][0], a);
            a = fmaf(c[mt][nt][1], c[mt][nt][1], a);
            b = fmaf(c[mt][nt][2], c[mt][nt][2], b);
            b = fmaf(c[mt][nt][3], c[mt][nt][3], b);
        }
        a += __shfl_xor_sync(0xffffffffu, a, 1);
        a += __shfl_xor_sync(0xffffffffu, a, 2);
        b += __shfl_xor_sync(0xffffffffu, b, 1);
        b += __shfl_xor_sync(0xffffffffu, b, 2);
        sA[mt] = a; sB[mt] = b;
    }
    __syncthreads();
    if (tig == 0){
        #pragma unroll
        for (int mt = 0; mt < 2; mt++){
            red[wid*32 + mt*16 + g]     = sA[mt];
            red[wid*32 + mt*16 + g + 8] = sB[mt];
        }
    }
    __syncthreads();
    const int pw = wid ^ 4;
    float rrA[2], rrB[2];
    #pragma unroll
    for (int mt = 0; mt < 2; mt++){
        float ta = red[wid*32 + mt*16 + g]     + red[pw*32 + mt*16 + g];
        float tb = red[wid*32 + mt*16 + g + 8] + red[pw*32 + mt*16 + g + 8];
        rrA[mt] = rsqrtf(ta*(1.f/128.f) + 1e-6f);
        rrB[mt] = rsqrtf(tb*(1.f/128.f) + 1e-6f);
    }

    const float* sc = (ht == 0) ? qsc : ksc;
    const float post = (ht == 0) ? (0.08838834764831845f * 1.4426950408889634f) : 1.f;
    __half* dst = ((ht == 0) ? g_qh : g_kh) + (size_t)nh*LL*DD;

    #pragma unroll
    for (int mt = 0; mt < 2; mt++){
        const int mA = m0 + m0w + mt*16 + g;
        const int mB = mA + 8;
        #pragma unroll
        for (int nt = 0; nt < 8; nt++){
            const int nl = n0w + nt*8 + 2*tig;
            const int d2 = nl >> 1;
            const float s0 = __ldg(sc + nl), s1 = __ldg(sc + nl + 1);
            {
                const float4 r = *(const float4*)(pe + ((size_t)mA*64 + d2)*4);
                float e = c[mt][nt][0]*rrA[mt]*s0;
                float o = c[mt][nt][1]*rrA[mt]*s1;
                *(uint32_t*)(dst + (size_t)mA*DD + nl)
                    = h2_u32(__floats2half2_rn((r.x*e + r.y*o)*post, (r.z*e + r.w*o)*post));
            }
            {
                const float4 r = *(const float4*)(pe + ((size_t)mB*64 + d2)*4);
                float e = c[mt][nt][2]*rrB[mt]*s0;
                float o = c[mt][nt][3]*rrB[mt]*s1;
                *(uint32_t*)(dst + (size_t)mB*DD + nl)
                    = h2_u32(__floats2half2_rn((r.x*e + r.y*o)*post, (r.z*e + r.w*o)*post));
            }
        }
    }
}

// ---------------- GEMM2: split-K (z in {0,1}), atomic accumulation --------
__global__ __launch_bounds__(256, 2)
void gemm2_f16(const __half* __restrict__ A, const __half* __restrict__ B,
               const float* __restrict__ bias, float* __restrict__ Cf,
               int N, int K, int NIT,
               const float* __restrict__ xres, const float* __restrict__ gate)
{
    extern __shared__ char smc[];
    const uint32_t smb = smem_u32(smc);
    const int tid  = threadIdx.x;
    const int wid  = tid >> 5;
    const int lane = tid & 31;
    const int g    = lane >> 2;
    const int tig  = lane & 3;
    const int m0 = blockIdx.x * 128;
    const int n0 = blockIdx.y * 128;
    const int kz = blockIdx.z;
    const int khalf = K >> 1;               // elements per split
    const int m0w = (wid & 3) * 32;
    const int n0w = (wid >> 2) * 64;

    const char* gp[8];
    uint32_t sof[8];
    size_t gstep[8];
    #pragma unroll
    for (int i = 0; i < 8; i++){
        int idx = i*256 + tid;
        if (idx < 1024){
            int row = idx >> 3, seg = idx & 7;
            gp[i]   = (const char*)(A + (size_t)(m0 + row)*K + (size_t)kz*khalf) + seg*16;
            sof[i]  = (uint32_t)(row*MG_ARB + seg*16);
            gstep[i] = 128;
        } else {
            int t = idx - 1024;
            int row = t >> 4, seg = t & 15;
            gp[i]   = (const char*)(B + (size_t)(kz*khalf + row)*N + n0) + seg*16;
            sof[i]  = (uint32_t)(G2_BOFF + row*MG_BRB + seg*16);
            gstep[i] = (size_t)64*N*2;
        }
    }

#define G2_LOAD(IT, ST) do { \
        const uint32_t _sb = smb + (uint32_t)(ST)*G2_STAGE; \
        _Pragma("unroll") \
        for (int _i = 0; _i < 8; _i++){ \
            asm volatile("cp.async.cg.shared.global [%0], [%1], 16;" \
                :: "r"(_sb + sof[_i]), "l"(gp[_i] + (size_t)(IT)*gstep[_i]) : "memory"); \
        } \
        asm volatile("cp.async.commit_group;" ::: "memory"); \
    } while(0)

    float c[2][8][4];
    #pragma unroll
    for (int mt = 0; mt < 2; mt++)
        #pragma unroll
        for (int nt = 0; nt < 8; nt++)
            #pragma unroll
            for (int q = 0; q < 4; q++) c[mt][nt][q] = 0.f;

    const uint32_t aoff  = (uint32_t)((lane & 15)*MG_ARB + ((lane >> 4) & 1)*16);
    const uint32_t boff4 = (uint32_t)(G2_BOFF + (lane & 15)*MG_BRB + ((lane >> 4) & 1)*16 + n0w*2);

    G2_LOAD(0, 0);
    G2_LOAD(1, 1);

    int s = 0, sl = 2;
    for (int it = 0; it < NIT; ++it){
        if (it == NIT-1) asm volatile("cp.async.wait_group 0;" ::: "memory");
        else             asm volatile("cp.async.wait_group 1;" ::: "memory");
        __syncthreads();
        if (it + 2 < NIT) G2_LOAD(it + 2, sl);

        const uint32_t sb = smb + (uint32_t)s*G2_STAGE;
        #pragma unroll
        for (int k16 = 0; k16 < 4; k16++){
            uint32_t a[2][4];
            #pragma unroll
            for (int mt = 0; mt < 2; mt++)
                ldsm_x4(a[mt], sb + (uint32_t)((m0w + mt*16)*MG_ARB) + aoff + k16*32);
            uint32_t b[8][2];
            #pragma unroll
            for (int u = 0; u < 4; u++)
                ldsm_x4t(&b[2*u][0], sb + boff4 + (uint32_t)(k16*16*MG_BRB) + u*32);
            #pragma unroll
            for (int mt = 0; mt < 2; mt++)
                #pragma unroll
                for (int nt = 0; nt < 8; nt++)
                    mma_f16(c[mt][nt], a[mt], b[nt]);
        }
        s  = (s  == 2) ? 0 : s  + 1;
        sl = (sl == 2) ? 0 : sl + 1;
    }

    // d_out was zero-initialized; exactly two commutative atomic adds per elem.
    #pragma unroll
    for (int mt = 0; mt < 2; mt++){
        const int m = m0 + m0w + mt*16 + g;
        #pragma unroll
        for (int nt = 0; nt < 8; nt++){
            const int n = n0 + n0w + nt*8 + 2*tig;
            const float g0 = __ldg(gate + n), g1 = __ldg(gate + n + 1);
            float v0, v1, v2, v3;
            if (kz == 0){
                const float b0 = __ldg(bias + n), b1 = __ldg(bias + n + 1);
                v0 = xres[(size_t)m*N + n]       + g0*(c[mt][nt][0] + b0);
                v1 = xres[(size_t)m*N + n + 1]   + g1*(c[mt][nt][1] + b1);
                v2 = xres[(size_t)(m+8)*N + n]   + g0*(c[mt][nt][2] + b0);
                v3 = xres[(size_t)(m+8)*N + n+1] + g1*(c[mt][nt][3] + b1);
            } else {
                v0 = g0*c[mt][nt][0];
                v1 = g1*c[mt][nt][1];
                v2 = g0*c[mt][nt][2];
                v3 = g1*c[mt][nt][3];
            }
            atomicAdd(Cf + (size_t)m*N + n,       v0);
            atomicAdd(Cf + (size_t)m*N + n + 1,   v1);
            atomicAdd(Cf + (size_t)(m+8)*N + n,   v2);
            atomicAdd(Cf + (size_t)(m+8)*N + n+1, v3);
        }
    }
}

// ---------------- flash attention: P in regs, f16x2 exp, 2-stage, occ 2 ----
#define AQ_RB 272
#define AKV0  (128*AQ_RB)
#define AKV_STAGE (64*AQ_RB*2)
#define AV_IN 17408
#define ATF_SMEM (AKV0 + 2*AKV_STAGE)
#define NKT (LL/64)

__global__ __launch_bounds__(256, 2)
void attn_f16(){
    extern __shared__ char smc[];
    const uint32_t smb = smem_u32(smc);
    const int tid  = threadIdx.x;
    const int wid  = tid >> 5;
    const int lane = tid & 31;
    const int nh = blockIdx.y;
    const int q0 = blockIdx.x * 128;
    const __half* Qh = g_qh + (size_t)nh*LL*DD;
    const __half* Kh = g_kh + (size_t)nh*LL*DD;
    const __half* Vh = g_vh + (size_t)nh*LL*DD;

#define ATT_LOAD(IT, ST) do { \
        const uint32_t _sb = smb + AKV0 + (uint32_t)(ST)*AKV_STAGE; \
        const __half* _kb = Kh + (size_t)(IT)*64*DD; \
        const __half* _vb = Vh + (size_t)(IT)*64*DD; \
        _Pragma("unroll") \
        for (int _i = 0; _i < 8; _i++){ \
            int _idx = _i*256 + tid; \
            int _t = _idx & 1023; \
            int _r = _t >> 4, _sg = _t & 15; \
            const char* _g = (const char*)((_idx < 1024 ? _kb : _vb) + (size_t)_r*DD) + _sg*16; \
            uint32_t _sa = _sb + (_idx < 1024 ? 0u : (uint32_t)AV_IN) + (uint32_t)(_r*AQ_RB + _sg*16); \
            asm volatile("cp.async.cg.shared.global [%0], [%1], 16;" :: "r"(_sa), "l"(_g) : "memory"); \
        } \
        asm volatile("cp.async.commit_group;" ::: "memory"); \
    } while(0)

    ATT_LOAD(0, 0);
    ATT_LOAD(1, 1);

    #pragma unroll
    for (int i = 0; i < 8; i++){
        int idx = i*256 + tid;
        int r = idx >> 4, s = idx & 15;
        uint4 v = *(const uint4*)((const char*)(Qh + (size_t)(q0+r)*DD) + s*16);
        *(uint4*)(smc + r*AQ_RB + s*16) = v;
    }

    float o[16][4];
    #pragma unroll
    for (int nt = 0; nt < 16; nt++)
        #pragma unroll
        for (int q = 0; q < 4; q++) o[nt][q] = 0.f;
    float m0 = -1e30f, m1 = -1e30f, l0 = 0.f, l1 = 0.f;

    const uint32_t aoffQ = smb + (uint32_t)((wid*16 + (lane & 15))*AQ_RB + ((lane >> 4) & 1)*16);
    const uint32_t kbase4 = (uint32_t)((((lane >> 4) & 1)*8 + (lane & 7))*AQ_RB + ((lane >> 3) & 1)*16);
    const uint32_t vbase4 = (uint32_t)((lane & 15)*AQ_RB + ((lane >> 4) & 1)*16);

    int st = 0;
    for (int kt = 0; kt < NKT; kt++){
        if (kt == NKT-1) asm volatile("cp.async.wait_group 0;" ::: "memory");
        else             asm volatile("cp.async.wait_group 1;" ::: "memory");
        __syncthreads();

        const uint32_t kvb = smb + AKV0 + (uint32_t)st*AKV_STAGE;

        float s[8][4];
        #pragma unroll
        for (int nt = 0; nt < 8; nt++)
            #pragma unroll
            for (int q = 0; q < 4; q++) s[nt][q] = 0.f;
        #pragma unroll
        for (int k16 = 0; k16 < 8; k16++){
            uint32_t a[4];
            ldsm_x4(a, aoffQ + k16*32);
            #pragma unroll
            for (int u = 0; u < 4; u++){
                uint32_t bb[4];
                ldsm_x4(bb, kvb + kbase4 + (uint32_t)(u*16*AQ_RB) + k16*32);
                mma_f16(s[2*u],   a, bb);
                mma_f16(s[2*u+1], a, bb+2);
            }
        }

        float mx0 = -1e30f, mx1 = -1e30f;
        #pragma unroll
        for (int nt = 0; nt < 8; nt++){
            mx0 = fmaxf(mx0, fmaxf(s[nt][0], s[nt][1]));
            mx1 = fmaxf(mx1, fmaxf(s[nt][2], s[nt][3]));
        }
        mx0 = fmaxf(mx0, __shfl_xor_sync(0xffffffffu, mx0, 1));
        mx0 = fmaxf(mx0, __shfl_xor_sync(0xffffffffu, mx0, 2));
        mx1 = fmaxf(mx1, __shfl_xor_sync(0xffffffffu, mx1, 1));
        mx1 = fmaxf(mx1, __shfl_xor_sync(0xffffffffu, mx1, 2));
        const float mn0 = fmaxf(m0, mx0), mn1 = fmaxf(m1, mx1);
        const float al0 = ex2f(m0 - mn0), al1 = ex2f(m1 - mn1);
        m0 = mn0; m1 = mn1;
        float rs0 = 0.f, rs1 = 0.f;
        uint32_t ph[8][2];
        #pragma unroll
        for (int nt = 0; nt < 8; nt++){
            ph[nt][0] = ex2_h2(h2_u32(__floats2half2_rn(s[nt][0]-mn0, s[nt][1]-mn0)));
            ph[nt][1] = ex2_h2(h2_u32(__floats2half2_rn(s[nt][2]-mn1, s[nt][3]-mn1)));
            float2 f0 = __half22float2(u32_h2(ph[nt][0]));
            float2 f1 = __half22float2(u32_h2(ph[nt][1]));
            rs0 += f0.x + f0.y;
            rs1 += f1.x + f1.y;
        }
        rs0 += __shfl_xor_sync(0xffffffffu, rs0, 1);
        rs0 += __shfl_xor_sync(0xffffffffu, rs0, 2);
        rs1 += __shfl_xor_sync(0xffffffffu, rs1, 1);
        rs1 += __shfl_xor_sync(0xffffffffu, rs1, 2);
        l0 = l0*al0 + rs0;
        l1 = l1*al1 + rs1;
        #pragma unroll
        for (int nt = 0; nt < 16; nt++){
            o[nt][0] *= al0; o[nt][1] *= al0;
            o[nt][2] *= al1; o[nt][3] *= al1;
        }

        #pragma unroll
        for (int c16 = 0; c16 < 4; c16++){
            uint32_t pa[4] = { ph[2*c16][0], ph[2*c16][1],
                               ph[2*c16+1][0], ph[2*c16+1][1] };
            #pragma unroll
            for (int u = 0; u < 8; u++){
                uint32_t bb[4];
                ldsm_x4t(bb, kvb + AV_IN + vbase4 + (uint32_t)(c16*16*AQ_RB) + u*32);
                mma_f16(o[2*u],   pa, bb);
                mma_f16(o[2*u+1], pa, bb+2);
            }
        }

        __syncthreads();
        if (kt + 2 < NKT) ATT_LOAD(kt + 2, st);
        st ^= 1;
    }

    const float rl0 = 1.0f / l0, rl1 = 1.0f / l1;
    const int g = lane >> 2, tig = lane & 3;
    const int r0 = q0 + wid*16 + g, r1 = r0 + 8;
    #pragma unroll
    for (int nt = 0; nt < 16; nt++){
        const int col = nh*DD + nt*8 + 2*tig;
        *(uint32_t*)(g_cath + (size_t)r0*CATN + col)
            = h2_u32(__floats2half2_rn(o[nt][0]*rl0, o[nt][1]*rl0));
        *(uint32_t*)(g_cath + (size_t)r1*CATN + col)
            = h2_u32(__floats2half2_rn(o[nt][2]*rl1, o[nt][3]*rl1));
    }
}

// ---------------- launch --------------------------------------------------
extern "C" void kernel_launch(void* const* d_in, const int* in_sizes, int n_in,
                              void* d_out, int out_size){
    (void)in_sizes; (void)n_in; (void)out_size;
    const float* x       = (const float*)d_in[0];
    const float* vec     = (const float*)d_in[1];
    const float* pe      = (const float*)d_in[2];
    const float* mod_w   = (const float*)d_in[3];
    const float* mod_b   = (const float*)d_in[4];
    const float* ln_s    = (const float*)d_in[5];
    const float* ln_b    = (const float*)d_in[6];
    const float* w1      = (const float*)d_in[7];
    const float* b1      = (const float*)d_in[8];
    const float* q_scale = (const float*)d_in[9];
    const float* k_scale = (const float*)d_in[10];
    const float* w2      = (const float*)d_in[11];
    const float* b2      = (const float*)d_in[12];
    float* out = (float*)d_out;

    float *p_mod;
    __half *p_xmodh, *p_cath, *p_w1h, *p_w2h;
    cudaGetSymbolAddress((void**)&p_xmodh, g_xmodh);
    cudaGetSymbolAddress((void**)&p_cath,  g_cath);
    cudaGetSymbolAddress((void**)&p_mod,   g_mod);
    cudaGetSymbolAddress((void**)&p_w1h,   g_w1h);
    cudaGetSymbolAddress((void**)&p_w2h,   g_w2h);

    cudaFuncSetAttribute(attn_f16, cudaFuncAttributeMaxDynamicSharedMemorySize, ATF_SMEM);
    cudaFuncSetAttribute(gemm1_f16, cudaFuncAttributeMaxDynamicSharedMemorySize, G2_SMEM);
    cudaFuncSetAttribute(gemm2_f16, cudaFuncAttributeMaxDynamicSharedMemorySize, G2_SMEM);

    prep<<<NB1 + NB2 + NBS + NBZ, 256>>>((const float4*)w1, (uint2*)p_w1h,
                                         (const float4*)w2, (uint2*)p_w2h,
                                         vec, mod_b, (float4*)out);
    mod_gemv<<<dim3(QKVN/1024, HH/256), 256>>>(mod_w);
    ln_mod  <<<LL, 384>>>(x, ln_s, ln_b);
    gemm1_f16<<<dim3(LL/128, W1N/128), 256, G2_SMEM>>>(p_xmodh, p_w1h, b1,
                                                       pe, q_scale, k_scale,
                                                       W1N, HH, HH/64);
    attn_f16<<<dim3(LL/128, NHH), 256, ATF_SMEM>>>();
    gemm2_f16<<<dim3(LL/128, HH/128, 2), 256, G2_SMEM>>>(p_cath, p_w2h, b2, out,
                                                         HH, CATN, CATN/128,
                                                         x, p_mod + 2*HH);
}

// round 17
// speedup vs baseline: 1.0252x; 1.0019x over previous
#include <cuda_runtime.h>
#include <cuda_fp16.h>
#include <cstdint>
#include <cstring>

#define LL   2048
#define HH   3072
#define NHH  24
#define DD   128
#define MLPD 12288
#define W1N  21504
#define CATN 15360
#define QKVN 9216

__device__ __forceinline__ uint32_t h2_u32(__half2 h){
    uint32_t u; memcpy(&u, &h, 4); return u;
}
__device__ __forceinline__ __half2 u32_h2(uint32_t u){
    __half2 h; memcpy(&h, &u, 4); return h;
}
__device__ __forceinline__ uint32_t smem_u32(const void* p){
    uint32_t a; asm("{ .reg .u64 t; cvta.to.shared.u64 t, %1; cvt.u32.u64 %0, t; }" : "=r"(a) : "l"(p));
    return a;
}
__device__ __forceinline__ float ex2f(float x){
    float r; asm("ex2.approx.f32 %0, %1;" : "=f"(r) : "f"(x)); return r;
}
__device__ __forceinline__ uint32_t ex2_h2(uint32_t x){
    uint32_t r; asm("ex2.approx.f16x2 %0, %1;" : "=r"(r) : "r"(x)); return r;
}
__device__ __forceinline__ float tanh_ap(float x){
    float r; asm("tanh.approx.f32 %0, %1;" : "=f"(r) : "f"(x)); return r;
}
__device__ __forceinline__ float gelu_f(float v){
    float c = 0.7978845608028654f * (v + 0.044715f*v*v*v);
    return 0.5f*v*(1.f + tanh_ap(c));
}
__device__ __forceinline__ void mma_f16(float* c, const uint32_t* a, const uint32_t* b){
    asm volatile("mma.sync.aligned.m16n8k16.row.col.f32.f16.f16.f32 "
        "{%0,%1,%2,%3}, {%4,%5,%6,%7}, {%8,%9}, {%0,%1,%2,%3};"
        : "+f"(c[0]), "+f"(c[1]), "+f"(c[2]), "+f"(c[3])
        : "r"(a[0]), "r"(a[1]), "r"(a[2]), "r"(a[3]), "r"(b[0]), "r"(b[1]));
}
__device__ __forceinline__ void ldsm_x4(uint32_t* r, uint32_t a){
    asm volatile("ldmatrix.sync.aligned.m8n8.x4.shared.b16 {%0,%1,%2,%3}, [%4];"
        : "=r"(r[0]), "=r"(r[1]), "=r"(r[2]), "=r"(r[3]) : "r"(a));
}
__device__ __forceinline__ void ldsm_x4t(uint32_t* r, uint32_t a){
    asm volatile("ldmatrix.sync.aligned.m8n8.x4.trans.shared.b16 {%0,%1,%2,%3}, [%4];"
        : "=r"(r[0]), "=r"(r[1]), "=r"(r[2]), "=r"(r[3]) : "r"(a));
}
__device__ __forceinline__ void cp16(uint32_t s, const void* g){
    asm volatile("cp.async.cg.shared.global [%0], [%1], 16;" :: "r"(s), "l"(g) : "memory");
}

// ---------------- scratch ----------------
__device__ float  g_sv[HH];
__device__ float  g_mod[3*HH];
__device__ __half g_xmodh[(size_t)LL*HH];
__device__ __half g_qh[(size_t)NHH*LL*DD];
__device__ __half g_kh[(size_t)NHH*LL*DD];
__device__ __half g_vh[(size_t)NHH*LL*DD];
__device__ __half g_cath[(size_t)LL*CATN];
__device__ __half g_w1h[(size_t)HH*W1N];
__device__ __half g_w2h[(size_t)CATN*HH];

// ---------------- prep: conv w1 + conv w2 + silu/mod + zero d_out ---------
#define N4W1 ((int)((size_t)HH*W1N/4))
#define N4W2 ((int)((size_t)CATN*HH/4))
#define NB1  ((N4W1 + 255)/256)
#define NB2  ((N4W2 + 255)/256)
#define NBS  ((QKVN + 255)/256)
#define NZ4  ((int)((size_t)LL*HH/4))
#define NBZ  ((NZ4 + 255)/256)
__global__ void prep(const float4* __restrict__ w1, uint2* __restrict__ o1,
                     const float4* __restrict__ w2, uint2* __restrict__ o2,
                     const float* __restrict__ vec, const float* __restrict__ b,
                     float4* __restrict__ outz){
    const int bid = blockIdx.x;
    const int tid = threadIdx.x;
    if (bid < NB1 + NB2){
        const bool w1p = bid < NB1;
        int i = (w1p ? bid : bid - NB1)*256 + tid;
        int n = w1p ? N4W1 : N4W2;
        if (i < n){
            float4 v = w1p ? w1[i] : w2[i];
            __half2 a = __floats2half2_rn(v.x, v.y);
            __half2 c = __floats2half2_rn(v.z, v.w);
            uint2 o; memcpy(&o.x, &a, 4); memcpy(&o.y, &c, 4);
            if (w1p) o1[i] = o; else o2[i] = o;
        }
    } else if (bid < NB1 + NB2 + NBS){
        int i = (bid - NB1 - NB2)*256 + tid;
        if (i < HH){
            float t = vec[i];
            g_sv[i] = t / (1.f + expf(-t));
        }
        if (i < QKVN) g_mod[i] = b[i];
    } else {
        int i = (bid - NB1 - NB2 - NBS)*256 + tid;
        if (i < NZ4) outz[i] = make_float4(0.f, 0.f, 0.f, 0.f);
    }
}

// ---------------- K-split GEMV (float4 per thread) ----------------
__global__ __launch_bounds__(256) void mod_gemv(const float* __restrict__ W){
    const int j  = (blockIdx.x*256 + threadIdx.x)*4;
    const int k0 = blockIdx.y*256;
    __shared__ float svs[256];
    svs[threadIdx.x] = g_sv[k0 + threadIdx.x];
    __syncthreads();
    float a0 = 0.f, a1 = 0.f, a2 = 0.f, a3 = 0.f;
    #pragma unroll 4
    for (int i = 0; i < 256; i++){
        float4 w = *(const float4*)(W + (size_t)(k0+i)*QKVN + j);
        a0 = fmaf(svs[i], w.x, a0);
        a1 = fmaf(svs[i], w.y, a1);
        a2 = fmaf(svs[i], w.z, a2);
        a3 = fmaf(svs[i], w.w, a3);
    }
    atomicAdd(&g_mod[j],   a0);
    atomicAdd(&g_mod[j+1], a1);
    atomicAdd(&g_mod[j+2], a2);
    atomicAdd(&g_mod[j+3], a3);
}

// ---------------- LayerNorm + modulate (half output, 384 thr) -------------
__global__ __launch_bounds__(384) void ln_mod(const float* __restrict__ x,
                                              const float* __restrict__ lns,
                                              const float* __restrict__ lnb){
    const int l = blockIdx.x;
    const int tid = threadIdx.x;
    __shared__ float xs[HH];
    __shared__ float rsum[24];
    float s = 0.f, ss = 0.f;
    #pragma unroll
    for (int t = 0; t < 2; t++){
        int i = tid*4 + t*1536;
        float4 v = *(const float4*)(x + (size_t)l*HH + i);
        *(float4*)(xs + i) = v;
        s += v.x + v.y + v.z + v.w;
        ss = fmaf(v.x, v.x, ss); ss = fmaf(v.y, v.y, ss);
        ss = fmaf(v.z, v.z, ss); ss = fmaf(v.w, v.w, ss);
    }
    #pragma unroll
    for (int w = 1; w < 32; w <<= 1){
        s  += __shfl_xor_sync(0xffffffffu, s,  w);
        ss += __shfl_xor_sync(0xffffffffu, ss, w);
    }
    int wid = tid >> 5;
    if ((tid & 31) == 0){ rsum[wid] = s; rsum[wid + 12] = ss; }
    __syncthreads();
    s = 0.f; ss = 0.f;
    #pragma unroll
    for (int w = 0; w < 12; w++){ s += rsum[w]; ss += rsum[w + 12]; }
    const float mu   = s  * (1.f/(float)HH);
    const float var  = ss * (1.f/(float)HH) - mu*mu;
    const float rstd = rsqrtf(var + 1e-6f);
    #pragma unroll
    for (int t = 0; t < 2; t++){
        int i = tid*4 + t*1536;
        float4 v  = *(const float4*)(xs + i);
        float4 lv = *(const float4*)(lns + i);
        float4 bv = *(const float4*)(lnb + i);
        float4 sc = *(const float4*)(g_mod + HH + i);
        float4 sh = *(const float4*)(g_mod + i);
        float o0 = (1.f+sc.x)*((v.x-mu)*rstd*lv.x + bv.x) + sh.x;
        float o1 = (1.f+sc.y)*((v.y-mu)*rstd*lv.y + bv.y) + sh.y;
        float o2 = (1.f+sc.z)*((v.z-mu)*rstd*lv.z + bv.z) + sh.z;
        float o3 = (1.f+sc.w)*((v.w-mu)*rstd*lv.w + bv.w) + sh.w;
        uint2 o;
        __half2 ha = __floats2half2_rn(o0, o1);
        __half2 hb = __floats2half2_rn(o2, o3);
        memcpy(&o.x, &ha, 4); memcpy(&o.y, &hb, 4);
        *(uint2*)(g_xmodh + (size_t)l*HH + i) = o;
    }
}

// ---------------- shared GEMM geometry: 128x128 tile, 3-stage, occ 2 ------
#define MG_ARB   144
#define MG_BRB   272
#define G2_BOFF  (128*MG_ARB)
#define G2_STAGE (G2_BOFF + 64*MG_BRB)        // 35840
#define G2_SMEM  (3*G2_STAGE)                 // 107520

// ---- templated mainloop: compile-time N/LDA/NIT -> loader state in 2 ptrs --
template<int N, int LDA, int NIT>
__device__ __forceinline__ void mm_main(char* smc,
                                        const __half* __restrict__ A,
                                        const __half* __restrict__ B,
                                        int m0, int n0, float (&c)[2][8][4])
{
    const uint32_t smb = smem_u32(smc);
    const int tid  = threadIdx.x;
    const int wid  = tid >> 5;
    const int lane = tid & 31;
    const int m0w = (wid & 3) * 32;
    const int n0w = (wid >> 2) * 64;

    const char* gpA = (const char*)(A + (size_t)(m0 + (tid >> 3))*LDA) + (tid & 7)*16;
    const char* gpB = (const char*)(B + (size_t)(tid >> 4)*N + n0) + (tid & 15)*16;
    const uint32_t sofA = (uint32_t)((tid >> 3)*MG_ARB + (tid & 7)*16);
    const uint32_t sofB = (uint32_t)(G2_BOFF + (tid >> 4)*MG_BRB + (tid & 15)*16);

#define MM_LOAD(IT, ST) do { \
        const uint32_t _sb = smb + (uint32_t)(ST)*G2_STAGE; \
        const char* _ga = gpA + (size_t)(IT)*128; \
        const char* _gb = gpB + (size_t)(IT)*((size_t)64*N*2); \
        _Pragma("unroll") \
        for (int _i = 0; _i < 4; _i++) \
            cp16(_sb + sofA + (uint32_t)(_i*32*MG_ARB), _ga + (size_t)_i*32*LDA*2); \
        _Pragma("unroll") \
        for (int _i = 0; _i < 4; _i++) \
            cp16(_sb + sofB + (uint32_t)(_i*16*MG_BRB), _gb + (size_t)_i*16*N*2); \
        asm volatile("cp.async.commit_group;" ::: "memory"); \
    } while(0)

    #pragma unroll
    for (int mt = 0; mt < 2; mt++)
        #pragma unroll
        for (int nt = 0; nt < 8; nt++)
            #pragma unroll
            for (int q = 0; q < 4; q++) c[mt][nt][q] = 0.f;

    const uint32_t aoff  = (uint32_t)((lane & 15)*MG_ARB + ((lane >> 4) & 1)*16);
    const uint32_t boff4 = (uint32_t)(G2_BOFF + (lane & 15)*MG_BRB + ((lane >> 4) & 1)*16 + n0w*2);

    MM_LOAD(0, 0);
    MM_LOAD(1, 1);

    int s = 0, sl = 2;
    for (int it = 0; it < NIT; ++it){
        if (it == NIT-1) asm volatile("cp.async.wait_group 0;" ::: "memory");
        else             asm volatile("cp.async.wait_group 1;" ::: "memory");
        __syncthreads();
        if (it + 2 < NIT) MM_LOAD(it + 2, sl);

        const uint32_t sb = smb + (uint32_t)s*G2_STAGE;
        #pragma unroll
        for (int k16 = 0; k16 < 4; k16++){
            uint32_t a[2][4];
            #pragma unroll
            for (int mt = 0; mt < 2; mt++)
                ldsm_x4(a[mt], sb + (uint32_t)((m0w + mt*16)*MG_ARB) + aoff + k16*32);
            uint32_t b[8][2];
            #pragma unroll
            for (int u = 0; u < 4; u++)
                ldsm_x4t(&b[2*u][0], sb + boff4 + (uint32_t)(k16*16*MG_BRB) + u*32);
            #pragma unroll
            for (int mt = 0; mt < 2; mt++)
                #pragma unroll
                for (int nt = 0; nt < 8; nt++)
                    mma_f16(c[mt][nt], a[mt], b[nt]);
        }
        s  = (s  == 2) ? 0 : s  + 1;
        sl = (sl == 2) ? 0 : sl + 1;
    }
#undef MM_LOAD
}

// ---------------- GEMM1: fused epilogue (qkv rmsnorm+rope | gelu) ---------
__global__ __launch_bounds__(256, 2)
void gemm1_f16(const __half* __restrict__ A, const __half* __restrict__ B,
               const float* __restrict__ bias,
               const float* __restrict__ pe,
               const float* __restrict__ qsc, const float* __restrict__ ksc)
{
    extern __shared__ char smc[];
    const int tid  = threadIdx.x;
    const int wid  = tid >> 5;
    const int lane = tid & 31;
    const int g    = lane >> 2;
    const int tig  = lane & 3;
    const int m0 = blockIdx.x * 128;
    const int n0 = blockIdx.y * 128;
    const int m0w = (wid & 3) * 32;
    const int n0w = (wid >> 2) * 64;

    float c[2][8][4];
    mm_main<W1N, HH, HH/64>(smc, A, B, m0, n0, c);

    #pragma unroll
    for (int nt = 0; nt < 8; nt++){
        const int n = n0 + n0w + nt*8 + 2*tig;
        const float b0 = __ldg(bias + n), b1 = __ldg(bias + n + 1);
        #pragma unroll
        for (int mt = 0; mt < 2; mt++){
            c[mt][nt][0] += b0; c[mt][nt][1] += b1;
            c[mt][nt][2] += b0; c[mt][nt][3] += b1;
        }
    }

    if (n0 >= QKVN){
        const int nc0 = HH + (n0 - QKVN);
        #pragma unroll
        for (int mt = 0; mt < 2; mt++){
            const int m = m0 + m0w + mt*16 + g;
            #pragma unroll
            for (int nt = 0; nt < 8; nt++){
                const int nl = n0w + nt*8 + 2*tig;
                float v0 = gelu_f(c[mt][nt][0]);
                float v1 = gelu_f(c[mt][nt][1]);
                float v2 = gelu_f(c[mt][nt][2]);
                float v3 = gelu_f(c[mt][nt][3]);
                *(uint32_t*)(g_cath + (size_t)m*CATN + nc0 + nl)
                    = h2_u32(__floats2half2_rn(v0, v1));
                *(uint32_t*)(g_cath + (size_t)(m+8)*CATN + nc0 + nl)
                    = h2_u32(__floats2half2_rn(v2, v3));
            }
        }
        return;
    }

    const int ht = n0 / HH;
    const int nh = (n0 - ht*HH) >> 7;

    if (ht == 2){
        __half* dst = g_vh + (size_t)nh*LL*DD;
        #pragma unroll
        for (int mt = 0; mt < 2; mt++){
            const int m = m0 + m0w + mt*16 + g;
            #pragma unroll
            for (int nt = 0; nt < 8; nt++){
                const int nl = n0w + nt*8 + 2*tig;
                *(uint32_t*)(dst + (size_t)m*DD + nl)
                    = h2_u32(__floats2half2_rn(c[mt][nt][0], c[mt][nt][1]));
                *(uint32_t*)(dst + (size_t)(m+8)*DD + nl)
                    = h2_u32(__floats2half2_rn(c[mt][nt][2], c[mt][nt][3]));
            }
        }
        return;
    }

    float* red = (float*)smc;
    float sA[2], sB[2];
    #pragma unroll
    for (int mt = 0; mt < 2; mt++){
        float a = 0.f, b = 0.f;
        #pragma unroll
        for (int nt = 0; nt < 8; nt++){
            a = fmaf(c[mt][nt][0], c[mt][nt][0], a);
            a = fmaf(c[mt][nt][1], c[mt][nt][1], a);
            b = fmaf(c[mt][nt][2], c[mt][nt][2], b);
            b = fmaf(c[mt][nt][3], c[mt][nt][3], b);
        }
        a += __shfl_xor_sync(0xffffffffu, a, 1);
        a += __shfl_xor_sync(0xffffffffu, a, 2);
        b += __shfl_xor_sync(0xffffffffu, b, 1);
        b += __shfl_xor_sync(0xffffffffu, b, 2);
        sA[mt] = a; sB[mt] = b;
    }
    __syncthreads();
    if (tig == 0){
        #pragma unroll
        for (int mt = 0; mt < 2; mt++){
            red[wid*32 + mt*16 + g]     = sA[mt];
            red[wid*32 + mt*16 + g + 8] = sB[mt];
        }
    }
    __syncthreads();
    const int pw = wid ^ 4;
    float rrA[2], rrB[2];
    #pragma unroll
    for (int mt = 0; mt < 2; mt++){
        float ta = red[wid*32 + mt*16 + g]     + red[pw*32 + mt*16 + g];
        float tb = red[wid*32 + mt*16 + g + 8] + red[pw*32 + mt*16 + g + 8];
        rrA[mt] = rsqrtf(ta*(1.f/128.f) + 1e-6f);
        rrB[mt] = rsqrtf(tb*(1.f/128.f) + 1e-6f);
    }

    const float* sc = (ht == 0) ? qsc : ksc;
    const float post = (ht == 0) ? (0.08838834764831845f * 1.4426950408889634f) : 1.f;
    __half* dst = ((ht == 0) ? g_qh : g_kh) + (size_t)nh*LL*DD;

    #pragma unroll
    for (int mt = 0; mt < 2; mt++){
        const int mA = m0 + m0w + mt*16 + g;
        const int mB = mA + 8;
        #pragma unroll
        for (int nt = 0; nt < 8; nt++){
            const int nl = n0w + nt*8 + 2*tig;
            const int d2 = nl >> 1;
            const float s0 = __ldg(sc + nl), s1 = __ldg(sc + nl + 1);
            {
                const float4 r = *(const float4*)(pe + ((size_t)mA*64 + d2)*4);
                float e = c[mt][nt][0]*rrA[mt]*s0;
                float o = c[mt][nt][1]*rrA[mt]*s1;
                *(uint32_t*)(dst + (size_t)mA*DD + nl)
                    = h2_u32(__floats2half2_rn((r.x*e + r.y*o)*post, (r.z*e + r.w*o)*post));
            }
            {
                const float4 r = *(const float4*)(pe + ((size_t)mB*64 + d2)*4);
                float e = c[mt][nt][2]*rrB[mt]*s0;
                float o = c[mt][nt][3]*rrB[mt]*s1;
                *(uint32_t*)(dst + (size_t)mB*DD + nl)
                    = h2_u32(__floats2half2_rn((r.x*e + r.y*o)*post, (r.z*e + r.w*o)*post));
            }
        }
    }
}

// ---------------- GEMM2: split-K (z in {0,1}), atomic accumulation --------
#define KHALF (CATN/2)
__global__ __launch_bounds__(256, 2)
void gemm2_f16(const __half* __restrict__ A, const __half* __restrict__ B,
               const float* __restrict__ bias, float* __restrict__ Cf,
               const float* __restrict__ xres, const float* __restrict__ gate)
{
    extern __shared__ char smc[];
    const int tid  = threadIdx.x;
    const int wid  = tid >> 5;
    const int lane = tid & 31;
    const int g    = lane >> 2;
    const int tig  = lane & 3;
    const int m0 = blockIdx.x * 128;
    const int n0 = blockIdx.y * 128;
    const int kz = blockIdx.z;
    const int m0w = (wid & 3) * 32;
    const int n0w = (wid >> 2) * 64;

    float c[2][8][4];
    mm_main<HH, CATN, KHALF/64>(smc, A + (size_t)kz*KHALF,
                                B + (size_t)kz*KHALF*HH, m0, n0, c);

    #pragma unroll
    for (int mt = 0; mt < 2; mt++){
        const int m = m0 + m0w + mt*16 + g;
        #pragma unroll
        for (int nt = 0; nt < 8; nt++){
            const int n = n0 + n0w + nt*8 + 2*tig;
            const float g0 = __ldg(gate + n), g1 = __ldg(gate + n + 1);
            float v0, v1, v2, v3;
            if (kz == 0){
                const float b0 = __ldg(bias + n), b1 = __ldg(bias + n + 1);
                v0 = xres[(size_t)m*HH + n]       + g0*(c[mt][nt][0] + b0);
                v1 = xres[(size_t)m*HH + n + 1]   + g1*(c[mt][nt][1] + b1);
                v2 = xres[(size_t)(m+8)*HH + n]   + g0*(c[mt][nt][2] + b0);
                v3 = xres[(size_t)(m+8)*HH + n+1] + g1*(c[mt][nt][3] + b1);
            } else {
                v0 = g0*c[mt][nt][0];
                v1 = g1*c[mt][nt][1];
                v2 = g0*c[mt][nt][2];
                v3 = g1*c[mt][nt][3];
            }
            atomicAdd(Cf + (size_t)m*HH + n,       v0);
            atomicAdd(Cf + (size_t)m*HH + n + 1,   v1);
            atomicAdd(Cf + (size_t)(m+8)*HH + n,   v2);
            atomicAdd(Cf + (size_t)(m+8)*HH + n+1, v3);
        }
    }
}

// ---------------- flash attention: P in regs, f16x2 exp, 2-stage, occ 2 ----
#define AQ_RB 272
#define AKV0  (128*AQ_RB)
#define AKV_STAGE (64*AQ_RB*2)
#define AV_IN 17408
#define ATF_SMEM (AKV0 + 2*AKV_STAGE)
#define NKT (LL/64)

__global__ __launch_bounds__(256, 2)
void attn_f16(){
    extern __shared__ char smc[];
    const uint32_t smb = smem_u32(smc);
    const int tid  = threadIdx.x;
    const int wid  = tid >> 5;
    const int lane = tid & 31;
    const int nh = blockIdx.y;
    const int q0 = blockIdx.x * 128;
    const __half* Qh = g_qh + (size_t)nh*LL*DD;
    const __half* Kh = g_kh + (size_t)nh*LL*DD;
    const __half* Vh = g_vh + (size_t)nh*LL*DD;

    // loader: base ptr + compile-time offsets (4 K rows + 4 V rows per thread)
    const char* gka = (const char*)(Kh + (size_t)(tid >> 4)*DD) + (tid & 15)*16;
    const char* gva = (const char*)(Vh + (size_t)(tid >> 4)*DD) + (tid & 15)*16;
    const uint32_t skv = (uint32_t)((tid >> 4)*AQ_RB + (tid & 15)*16);

#define ATT_LOAD(IT, ST) do { \
        const uint32_t _sb = smb + AKV0 + (uint32_t)(ST)*AKV_STAGE; \
        const char* _gk = gka + (size_t)(IT)*16384; \
        const char* _gv = gva + (size_t)(IT)*16384; \
        _Pragma("unroll") \
        for (int _i = 0; _i < 4; _i++) \
            cp16(_sb + skv + (uint32_t)(_i*16*AQ_RB), _gk + (size_t)_i*4096); \
        _Pragma("unroll") \
        for (int _i = 0; _i < 4; _i++) \
            cp16(_sb + (uint32_t)AV_IN + skv + (uint32_t)(_i*16*AQ_RB), _gv + (size_t)_i*4096); \
        asm volatile("cp.async.commit_group;" ::: "memory"); \
    } while(0)

    ATT_LOAD(0, 0);
    ATT_LOAD(1, 1);

    #pragma unroll
    for (int i = 0; i < 8; i++){
        int idx = i*256 + tid;
        int r = idx >> 4, s = idx & 15;
        uint4 v = *(const uint4*)((const char*)(Qh + (size_t)(q0+r)*DD) + s*16);
        *(uint4*)(smc + r*AQ_RB + s*16) = v;
    }

    float o[16][4];
    #pragma unroll
    for (int nt = 0; nt < 16; nt++)
        #pragma unroll
        for (int q = 0; q < 4; q++) o[nt][q] = 0.f;
    float m0 = -1e30f, m1 = -1e30f, l0 = 0.f, l1 = 0.f;

    const uint32_t aoffQ = smb + (uint32_t)((wid*16 + (lane & 15))*AQ_RB + ((lane >> 4) & 1)*16);
    const uint32_t kbase4 = (uint32_t)((((lane >> 4) & 1)*8 + (lane & 7))*AQ_RB + ((lane >> 3) & 1)*16);
    const uint32_t vbase4 = (uint32_t)((lane & 15)*AQ_RB + ((lane >> 4) & 1)*16);

    int st = 0;
    for (int kt = 0; kt < NKT; kt++){
        if (kt == NKT-1) asm volatile("cp.async.wait_group 0;" ::: "memory");
        else             asm volatile("cp.async.wait_group 1;" ::: "memory");
        __syncthreads();

        const uint32_t kvb = smb + AKV0 + (uint32_t)st*AKV_STAGE;

        float s[8][4];
        #pragma unroll
        for (int nt = 0; nt < 8; nt++)
            #pragma unroll
            for (int q = 0; q < 4; q++) s[nt][q] = 0.f;
        #pragma unroll
        for (int k16 = 0; k16 < 8; k16++){
            uint32_t a[4];
            ldsm_x4(a, aoffQ + k16*32);
            #pragma unroll
            for (int u = 0; u < 4; u++){
                uint32_t bb[4];
                ldsm_x4(bb, kvb + kbase4 + (uint32_t)(u*16*AQ_RB) + k16*32);
                mma_f16(s[2*u],   a, bb);
                mma_f16(s[2*u+1], a, bb+2);
            }
        }

        float mx0 = -1e30f, mx1 = -1e30f;
        #pragma unroll
        for (int nt = 0; nt < 8; nt++){
            mx0 = fmaxf(mx0, fmaxf(s[nt][0], s[nt][1]));
            mx1 = fmaxf(mx1, fmaxf(s[nt][2], s[nt][3]));
        }
        mx0 = fmaxf(mx0, __shfl_xor_sync(0xffffffffu, mx0, 1));
        mx0 = fmaxf(mx0, __shfl_xor_sync(0xffffffffu, mx0, 2));
        mx1 = fmaxf(mx1, __shfl_xor_sync(0xffffffffu, mx1, 1));
        mx1 = fmaxf(mx1, __shfl_xor_sync(0xffffffffu, mx1, 2));
        const float mn0 = fmaxf(m0, mx0), mn1 = fmaxf(m1, mx1);
        const float al0 = ex2f(m0 - mn0), al1 = ex2f(m1 - mn1);
        m0 = mn0; m1 = mn1;
        float rs0 = 0.f, rs1 = 0.f;
        uint32_t ph[8][2];
        #pragma unroll
        for (int nt = 0; nt < 8; nt++){
            ph[nt][0] = ex2_h2(h2_u32(__floats2half2_rn(s[nt][0]-mn0, s[nt][1]-mn0)));
            ph[nt][1] = ex2_h2(h2_u32(__floats2half2_rn(s[nt][2]-mn1, s[nt][3]-mn1)));
            float2 f0 = __half22float2(u32_h2(ph[nt][0]));
            float2 f1 = __half22float2(u32_h2(ph[nt][1]));
            rs0 += f0.x + f0.y;
            rs1 += f1.x + f1.y;
        }
        rs0 += __shfl_xor_sync(0xffffffffu, rs0, 1);
        rs0 += __shfl_xor_sync(0xffffffffu, rs0, 2);
        rs1 += __shfl_xor_sync(0xffffffffu, rs1, 1);
        rs1 += __shfl_xor_sync(0xffffffffu, rs1, 2);
        l0 = l0*al0 + rs0;
        l1 = l1*al1 + rs1;
        #pragma unroll
        for (int nt = 0; nt < 16; nt++){
            o[nt][0] *= al0; o[nt][1] *= al0;
            o[nt][2] *= al1; o[nt][3] *= al1;
        }

        #pragma unroll
        for (int c16 = 0; c16 < 4; c16++){
            uint32_t pa[4] = { ph[2*c16][0], ph[2*c16][1],
                               ph[2*c16+1][0], ph[2*c16+1][1] };
            #pragma unroll
            for (int u = 0; u < 8; u++){
                uint32_t bb[4];
                ldsm_x4t(bb, kvb + AV_IN + vbase4 + (uint32_t)(c16*16*AQ_RB) + u*32);
                mma_f16(o[2*u],   pa, bb);
                mma_f16(o[2*u+1], pa, bb+2);
            }
        }

        __syncthreads();
        if (kt + 2 < NKT) ATT_LOAD(kt + 2, st);
        st ^= 1;
    }

    const float rl0 = 1.0f / l0, rl1 = 1.0f / l1;
    const int g = lane >> 2, tig = lane & 3;
    const int r0 = q0 + wid*16 + g, r1 = r0 + 8;
    #pragma unroll
    for (int nt = 0; nt < 16; nt++){
        const int col = nh*DD + nt*8 + 2*tig;
        *(uint32_t*)(g_cath + (size_t)r0*CATN + col)
            = h2_u32(__floats2half2_rn(o[nt][0]*rl0, o[nt][1]*rl0));
        *(uint32_t*)(g_cath + (size_t)r1*CATN + col)
            = h2_u32(__floats2half2_rn(o[nt][2]*rl1, o[nt][3]*rl1));
    }
}

// ---------------- launch --------------------------------------------------
extern "C" void kernel_launch(void* const* d_in, const int* in_sizes, int n_in,
                              void* d_out, int out_size){
    (void)in_sizes; (void)n_in; (void)out_size;
    const float* x       = (const float*)d_in[0];
    const float* vec     = (const float*)d_in[1];
    const float* pe      = (const float*)d_in[2];
    const float* mod_w   = (const float*)d_in[3];
    const float* mod_b   = (const float*)d_in[4];
    const float* ln_s    = (const float*)d_in[5];
    const float* ln_b    = (const float*)d_in[6];
    const float* w1      = (const float*)d_in[7];
    const float* b1      = (const float*)d_in[8];
    const float* q_scale = (const float*)d_in[9];
    const float* k_scale = (const float*)d_in[10];
    const float* w2      = (const float*)d_in[11];
    const float* b2      = (const float*)d_in[12];
    float* out = (float*)d_out;

    float *p_mod;
    __half *p_xmodh, *p_cath, *p_w1h, *p_w2h;
    cudaGetSymbolAddress((void**)&p_xmodh, g_xmodh);
    cudaGetSymbolAddress((void**)&p_cath,  g_cath);
    cudaGetSymbolAddress((void**)&p_mod,   g_mod);
    cudaGetSymbolAddress((void**)&p_w1h,   g_w1h);
    cudaGetSymbolAddress((void**)&p_w2h,   g_w2h);

    cudaFuncSetAttribute(attn_f16, cudaFuncAttributeMaxDynamicSharedMemorySize, ATF_SMEM);
    cudaFuncSetAttribute(gemm1_f16, cudaFuncAttributeMaxDynamicSharedMemorySize, G2_SMEM);
    cudaFuncSetAttribute(gemm2_f16, cudaFuncAttributeMaxDynamicSharedMemorySize, G2_SMEM);

    prep<<<NB1 + NB2 + NBS + NBZ, 256>>>((const float4*)w1, (uint2*)p_w1h,
                                         (const float4*)w2, (uint2*)p_w2h,
                                         vec, mod_b, (float4*)out);
    mod_gemv<<<dim3(QKVN/1024, HH/256), 256>>>(mod_w);
    ln_mod  <<<LL, 384>>>(x, ln_s, ln_b);
    gemm1_f16<<<dim3(LL/128, W1N/128), 256, G2_SMEM>>>(p_xmodh, p_w1h, b1,
                                                       pe, q_scale, k_scale);
    attn_f16<<<dim3(LL/128, NHH), 256, ATF_SMEM>>>();
    gemm2_f16<<<dim3(LL/128, HH/128, 2), 256, G2_SMEM>>>(p_cath, p_w2h, b2, out,
                                                         x, p_mod + 2*HH);
}